// round 8
// baseline (speedup 1.0000x reference)
#include <cuda_runtime.h>
#include <cuda_fp16.h>
#include <cstdint>
#include <math.h>

// ---------------- problem constants ----------------
constexpr int NB   = 32;
constexpr int NC   = 768;
constexpr int CIN0 = 80;
constexpr int T0   = 1024;
constexpr int T1   = 1022;
constexpr int T2   = 511;
constexpr int ND   = 64;
constexpr int NM   = 512;
constexpr int NQ   = NB * T2;
constexpr int NQE  = NQ * ND;
constexpr float BN_EPS = 1e-5f;
constexpr float WSCALE = 1024.0f;   // weight pre-scale to keep fp16 lo out of subnormals

// smem: 2 stages x (Ah, Al, Bh, Bl), each 128 rows x 40 halves = 10240 B
constexpr int LDH        = 40;       // halves per smem row (padded for bank-conflict-free frags)
constexpr int BUF_BYTES  = 4 * 128 * LDH * 2;   // 40960
constexpr int SMEM_BYTES = 2 * BUF_BYTES;       // 81920

// ---------------- scratch ----------------
__device__ float g_bufA[NB * NC * T1];
__device__ float g_bufB[NB * NC * T1];
__device__ float g_z[NQE];
__device__ float g_dist[NQ * NM];
__device__ float g_bnInv[5 * NC];
__device__ float g_bnBeta[5 * NC];
__device__ float g_e2[NM];
__device__ int   g_counts[NM];
__device__ float g_loss[1];

// ---------------- helpers ----------------
// split fp32 pair -> packed fp16x2 hi and lo (lo = residual, ~11 extra bits)
__device__ __forceinline__ void split2h(float a, float b, uint32_t& hi, uint32_t& lo) {
    __half ha = __float2half_rn(a);
    __half hb = __float2half_rn(b);
    float ra = a - __half2float(ha);
    float rb = b - __half2float(hb);
    __half la = __float2half_rn(ra);
    __half lb = __float2half_rn(rb);
    hi = ((uint32_t)__half_as_ushort(hb) << 16) | (uint32_t)__half_as_ushort(ha);
    lo = ((uint32_t)__half_as_ushort(lb) << 16) | (uint32_t)__half_as_ushort(la);
}

__device__ __forceinline__ void mma16816(float* c, const uint32_t* a, const uint32_t* b) {
    asm volatile(
        "mma.sync.aligned.m16n8k16.row.col.f32.f16.f16.f32 "
        "{%0,%1,%2,%3}, {%4,%5,%6,%7}, {%8,%9}, {%0,%1,%2,%3};"
        : "+f"(c[0]), "+f"(c[1]), "+f"(c[2]), "+f"(c[3])
        : "r"(a[0]), "r"(a[1]), "r"(a[2]), "r"(a[3]), "r"(b[0]), "r"(b[1]));
}

// ---------------- tiny prep kernels ----------------
__global__ void zero_k() {
    int i = threadIdx.x;
    if (i < NM) g_counts[i] = 0;
    if (i == NM) g_loss[0] = 0.f;
}

__global__ void bnprep_k(const float* __restrict__ g, const float* __restrict__ b,
                         const float* __restrict__ m, const float* __restrict__ v) {
    int i = blockIdx.x * blockDim.x + threadIdx.x;
    if (i < 5 * NC) {
        float inv = g[i] * rsqrtf(v[i] + BN_EPS);
        g_bnInv[i]  = inv / WSCALE;          // fold weight pre-scale back out
        g_bnBeta[i] = b[i] - m[i] * inv;
    }
}

__global__ void e2_k(const float* __restrict__ emb) {
    int e = blockIdx.x * blockDim.x + threadIdx.x;
    if (e < NM) {
        float s = 0.f;
        #pragma unroll
        for (int d = 0; d < ND; d++) { float t = emb[e * ND + d]; s += t * t; }
        g_e2[e] = s;
    }
}

// ---------------- conv1d + BN + ReLU via mma.sync, fp16 split 3-term ----------------
// D[m][n] = sum_kk A[m][kk]*B[n][kk];  A = w[Cout][CIN*KW] (x WSCALE), B = im2col(x)
template<int KW, int STRIDE, int PAD, int CIN, int TIN, int TOUT>
__device__ __forceinline__
void conv_mma_body(const float* __restrict__ x, const float* __restrict__ w,
                   const float* __restrict__ inv, const float* __restrict__ bet,
                   float* __restrict__ out)
{
    constexpr int KK    = CIN * KW;
    constexpr int NS    = (KK + 31) / 32;
    constexpr int NCOLS = NB * TOUT;

    extern __shared__ char smem[];

    const int tid  = threadIdx.x;
    const int lane = tid & 31;
    const int warp = tid >> 5;
    const int gid  = lane >> 2;     // 0..7
    const int tig  = lane & 3;      // 0..3
    const int mw   = warp >> 2;     // 0..1  (M-warp)
    const int nw   = warp & 3;      // 0..3  (N-warp)
    const int m0 = blockIdx.y * 128;
    const int n0 = blockIdx.x * 128;

    // staging maps
    const int arow = tid >> 1;               // 0..127 (weight row)
    const int ak0  = (tid & 1) * 16;         // 0 or 16
    const int bn   = tid & 127;              // 0..127 (B tile n-row)
    const int bk0  = (tid >> 7) * 16;        // 0 or 16
    const int ncolB = n0 + bn;
    const bool cv   = ncolB < NCOLS;
    const int nbB = cv ? (ncolB / TOUT) : 0;
    const int tB  = cv ? (ncolB - nbB * TOUT) : 0;
    const float* xrow = x + (size_t)nbB * CIN * TIN;
    const float* wrow = w + (size_t)(m0 + arow) * KK;

    float ar[16], br[16];
    float acc[4][4][4];
    #pragma unroll
    for (int a = 0; a < 4; a++)
        #pragma unroll
        for (int b = 0; b < 4; b++)
            #pragma unroll
            for (int c = 0; c < 4; c++) acc[a][b][c] = 0.f;

    auto LOADS = [&](int kt) {
        #pragma unroll
        for (int j = 0; j < 4; j++) {
            int kk = kt + ak0 + j * 4;
            if (kk + 3 < KK) {
                float4 v = *(const float4*)(wrow + kk);
                ar[j*4+0] = v.x; ar[j*4+1] = v.y; ar[j*4+2] = v.z; ar[j*4+3] = v.w;
            } else {
                #pragma unroll
                for (int q = 0; q < 4; q++)
                    ar[j*4+q] = (kk + q < KK) ? wrow[kk + q] : 0.f;
            }
        }
        #pragma unroll
        for (int i = 0; i < 16; i++) {
            int kk = kt + bk0 + i;
            float v = 0.f;
            if (cv && kk < KK) {
                int ci = kk / KW, kp = kk - ci * KW;
                int tin = tB * STRIDE + kp - PAD;
                if (tin >= 0 && tin < TIN) v = xrow[(size_t)ci * TIN + tin];
            }
            br[i] = v;
        }
    };

    auto STORES = [&](int s) {
        __half* Ah = (__half*)(smem + s * BUF_BYTES);
        __half* Al = Ah + 128 * LDH;
        __half* Bh = Al + 128 * LDH;
        __half* Bl = Bh + 128 * LDH;
        #pragma unroll
        for (int i = 0; i < 8; i++) {
            uint32_t hi, lo;
            split2h(ar[2*i] * WSCALE, ar[2*i+1] * WSCALE, hi, lo);
            *(uint32_t*)&Ah[arow * LDH + ak0 + 2*i] = hi;
            *(uint32_t*)&Al[arow * LDH + ak0 + 2*i] = lo;
            split2h(br[2*i], br[2*i+1], hi, lo);
            *(uint32_t*)&Bh[bn * LDH + bk0 + 2*i] = hi;
            *(uint32_t*)&Bl[bn * LDH + bk0 + 2*i] = lo;
        }
    };

    auto COMPUTE = [&](int s) {
        const __half* Ah = (const __half*)(smem + s * BUF_BYTES);
        const __half* Al = Ah + 128 * LDH;
        const __half* Bh = Al + 128 * LDH;
        const __half* Bl = Bh + 128 * LDH;
        #pragma unroll
        for (int kh = 0; kh < 2; kh++) {
            const int k16 = kh * 16;
            uint32_t aH[4][4], aL[4][4], bH[4][2], bL[4][2];
            #pragma unroll
            for (int mi = 0; mi < 4; mi++) {
                int r = mw * 64 + mi * 16 + gid;
                aH[mi][0] = *(const uint32_t*)&Ah[ r      * LDH + k16 + 2*tig    ];
                aH[mi][1] = *(const uint32_t*)&Ah[(r + 8) * LDH + k16 + 2*tig    ];
                aH[mi][2] = *(const uint32_t*)&Ah[ r      * LDH + k16 + 2*tig + 8];
                aH[mi][3] = *(const uint32_t*)&Ah[(r + 8) * LDH + k16 + 2*tig + 8];
                aL[mi][0] = *(const uint32_t*)&Al[ r      * LDH + k16 + 2*tig    ];
                aL[mi][1] = *(const uint32_t*)&Al[(r + 8) * LDH + k16 + 2*tig    ];
                aL[mi][2] = *(const uint32_t*)&Al[ r      * LDH + k16 + 2*tig + 8];
                aL[mi][3] = *(const uint32_t*)&Al[(r + 8) * LDH + k16 + 2*tig + 8];
            }
            #pragma unroll
            for (int ni = 0; ni < 4; ni++) {
                int n = nw * 32 + ni * 8 + gid;
                bH[ni][0] = *(const uint32_t*)&Bh[n * LDH + k16 + 2*tig    ];
                bH[ni][1] = *(const uint32_t*)&Bh[n * LDH + k16 + 2*tig + 8];
                bL[ni][0] = *(const uint32_t*)&Bl[n * LDH + k16 + 2*tig    ];
                bL[ni][1] = *(const uint32_t*)&Bl[n * LDH + k16 + 2*tig + 8];
            }
            #pragma unroll
            for (int mi = 0; mi < 4; mi++)
                #pragma unroll
                for (int ni = 0; ni < 4; ni++) {
                    mma16816(acc[mi][ni], aH[mi], bH[ni]);
                    mma16816(acc[mi][ni], aH[mi], bL[ni]);
                    mma16816(acc[mi][ni], aL[mi], bH[ni]);
                }
        }
    };

    LOADS(0);
    STORES(0);
    __syncthreads();
    for (int s = 0; s < NS; s++) {
        if (s + 1 < NS) LOADS((s + 1) * 32);
        COMPUTE(s & 1);
        if (s + 1 < NS) STORES((s + 1) & 1);
        __syncthreads();
    }

    // epilogue: BN + ReLU from accumulators, scalar stores (32B-sector friendly)
    #pragma unroll
    for (int mi = 0; mi < 4; mi++) {
        int r1 = m0 + mw * 64 + mi * 16 + gid;
        int r2 = r1 + 8;
        float iv1 = inv[r1], bb1 = bet[r1];
        float iv2 = inv[r2], bb2 = bet[r2];
        #pragma unroll
        for (int ni = 0; ni < 4; ni++) {
            int nc = n0 + nw * 32 + ni * 8 + 2 * tig;
            #pragma unroll
            for (int q = 0; q < 2; q++) {
                int ncol = nc + q;
                if (ncol < NCOLS) {
                    int nb = ncol / TOUT, t = ncol - nb * TOUT;
                    float v1 = acc[mi][ni][q]     * iv1 + bb1;
                    float v2 = acc[mi][ni][2 + q] * iv2 + bb2;
                    out[((size_t)nb * NC + r1) * TOUT + t] = v1 > 0.f ? v1 : 0.f;
                    out[((size_t)nb * NC + r2) * TOUT + t] = v2 > 0.f ? v2 : 0.f;
                }
            }
        }
    }
}

// ---- non-template global wrappers ----
__global__ __launch_bounds__(256)
void conv1_k(const float* __restrict__ x, const float* __restrict__ w,
             const float* __restrict__ inv, const float* __restrict__ bet,
             float* __restrict__ out) {
    conv_mma_body<3, 1, 0, CIN0, T0, T1>(x, w, inv, bet, out);
}
__global__ __launch_bounds__(256)
void conv2_k(const float* __restrict__ x, const float* __restrict__ w,
             const float* __restrict__ inv, const float* __restrict__ bet,
             float* __restrict__ out) {
    conv_mma_body<3, 1, 1, NC, T1, T1>(x, w, inv, bet, out);
}
__global__ __launch_bounds__(256)
void conv3_k(const float* __restrict__ x, const float* __restrict__ w,
             const float* __restrict__ inv, const float* __restrict__ bet,
             float* __restrict__ out) {
    conv_mma_body<4, 2, 1, NC, T1, T2>(x, w, inv, bet, out);
}
__global__ __launch_bounds__(256)
void conv45_k(const float* __restrict__ x, const float* __restrict__ w,
              const float* __restrict__ inv, const float* __restrict__ bet,
              float* __restrict__ out) {
    conv_mma_body<3, 1, 1, NC, T2, T2>(x, w, inv, bet, out);
}

// ---------------- 1x1 projection + bias + transpose to [B, T', D] (fp32) ----------------
__global__ __launch_bounds__(256)
void conv6_k(const float* __restrict__ x, const float* __restrict__ w6,
             const float* __restrict__ b6, float* __restrict__ z)
{
    __shared__ float Xs[16][64];
    __shared__ float Ws[16][65];
    const int tx = threadIdx.x, ty = threadIdx.y;
    const int tid = ty * 16 + tx;
    const int t0 = blockIdx.x * 64;
    const int b  = blockIdx.y;

    float acc[4][4] = {};
    for (int c0 = 0; c0 < NC; c0 += 16) {
        #pragma unroll
        for (int j = 0; j < 4; j++) {
            int idx = tid + j * 256;
            int tl = idx & 63, kk = idx >> 6;
            int t = t0 + tl;
            Xs[kk][tl] = (t < T2) ? x[((size_t)b * NC + c0 + kk) * T2 + t] : 0.f;
        }
        #pragma unroll
        for (int j = 0; j < 4; j++) {
            int idx = tid + j * 256;
            int dl = idx & 63, kk = idx >> 6;
            Ws[kk][dl] = w6[dl * NC + c0 + kk];
        }
        __syncthreads();
        #pragma unroll
        for (int k = 0; k < 16; k++) {
            float a[4], wv[4];
            #pragma unroll
            for (int i = 0; i < 4; i++) a[i] = Xs[k][ty * 4 + i];
            #pragma unroll
            for (int j = 0; j < 4; j++) wv[j] = Ws[k][tx * 4 + j];
            #pragma unroll
            for (int i = 0; i < 4; i++)
                #pragma unroll
                for (int j = 0; j < 4; j++)
                    acc[i][j] = fmaf(a[i], wv[j], acc[i][j]);
        }
        __syncthreads();
    }
    #pragma unroll
    for (int i = 0; i < 4; i++) {
        int t = t0 + ty * 4 + i;
        if (t < T2) {
            #pragma unroll
            for (int j = 0; j < 4; j++) {
                int d = tx * 4 + j;
                z[((size_t)b * T2 + t) * ND + d] = acc[i][j] + b6[d];
            }
        }
    }
}

// ---------------- VQ distance GEMM (fp32) ----------------
__global__ __launch_bounds__(256)
void dist_k(const float* __restrict__ emb)
{
    __shared__ float zs[64][65];
    __shared__ float es[64][65];
    const int tx = threadIdx.x, ty = threadIdx.y;
    const int tid = ty * 16 + tx;
    const int row0 = blockIdx.x * 64;
    const int e0   = blockIdx.y * 64;

    #pragma unroll
    for (int j = 0; j < 16; j++) {
        int idx = tid + j * 256;
        int k = idx & 63, r = idx >> 6;
        zs[r][k] = (row0 + r < NQ) ? g_z[(size_t)(row0 + r) * ND + k] : 0.f;
    }
    #pragma unroll
    for (int j = 0; j < 16; j++) {
        int idx = tid + j * 256;
        int k = idx & 63, e = idx >> 6;
        es[e][k] = emb[(size_t)(e0 + e) * ND + k];
    }
    __syncthreads();

    float acc[4][4] = {};
    #pragma unroll
    for (int k = 0; k < 64; k++) {
        float a[4], b[4];
        #pragma unroll
        for (int i = 0; i < 4; i++) a[i] = zs[ty * 4 + i][k];
        #pragma unroll
        for (int j = 0; j < 4; j++) b[j] = es[tx * 4 + j][k];
        #pragma unroll
        for (int i = 0; i < 4; i++)
            #pragma unroll
            for (int j = 0; j < 4; j++)
                acc[i][j] = fmaf(a[i], b[j], acc[i][j]);
    }

    #pragma unroll
    for (int i = 0; i < 4; i++) {
        int row = row0 + ty * 4 + i;
        if (row < NQ) {
            #pragma unroll
            for (int j = 0; j < 4; j++) {
                int e = e0 + tx * 4 + j;
                g_dist[(size_t)row * NM + e] = g_e2[e] - 2.f * acc[i][j];
            }
        }
    }
}

// ---------------- argmin + quantize + loss + counts ----------------
__global__ __launch_bounds__(256)
void vq_k(const float* __restrict__ emb, float* __restrict__ out_q)
{
    const int warp = threadIdx.x >> 5;
    const int lane = threadIdx.x & 31;
    const int row = blockIdx.x * 8 + warp;
    const float* dr = g_dist + (size_t)row * NM;

    float best = 3.4e38f; int bi = NM;
    #pragma unroll
    for (int i = 0; i < 16; i++) {
        int e = i * 32 + lane;
        float v = dr[e];
        if (v < best) { best = v; bi = e; }
    }
    #pragma unroll
    for (int off = 16; off > 0; off >>= 1) {
        float ob = __shfl_down_sync(0xffffffffu, best, off);
        int   oi = __shfl_down_sync(0xffffffffu, bi,   off);
        if (ob < best || (ob == best && oi < bi)) { best = ob; bi = oi; }
    }
    bi = __shfl_sync(0xffffffffu, bi, 0);

    const float* zr = g_z + (size_t)row * ND;
    const float* er = emb + (size_t)bi * ND;
    float lsum = 0.f;
    #pragma unroll
    for (int d0 = 0; d0 < ND; d0 += 32) {
        int d = d0 + lane;
        float zv = zr[d], qv = er[d];
        out_q[(size_t)row * ND + d] = zv + (qv - zv);
        float df = zv - qv;
        lsum += df * df;
    }
    #pragma unroll
    for (int off = 16; off > 0; off >>= 1)
        lsum += __shfl_down_sync(0xffffffffu, lsum, off);
    if (lane == 0) {
        atomicAdd(&g_loss[0], lsum);
        atomicAdd(&g_counts[bi], 1);
    }
}

__global__ void finalize_k(float* __restrict__ out)
{
    __shared__ float sh[NM];
    int tid = threadIdx.x;
    float p = (float)g_counts[tid] / (float)NQ;
    sh[tid] = -p * logf(p + 1e-10f);
    __syncthreads();
    for (int s = NM / 2; s > 0; s >>= 1) {
        if (tid < s) sh[tid] += sh[tid + s];
        __syncthreads();
    }
    if (tid == 0) {
        out[NQE]     = 0.25f * g_loss[0] / (float)NQE;
        out[NQE + 1] = expf(sh[0]);
    }
}

// ---------------- host-side driver ----------------
static void encoder_run(const float* mels, const float* w1, const float* w2,
                        const float* w3, const float* w4, const float* w5,
                        const float* w6, const float* b6,
                        const float* bng, const float* bnb,
                        const float* bnm, const float* bnv,
                        const float* emb, float* out)
{
    float *bufA, *bufB, *zbuf, *bnInv, *bnBeta;
    cudaGetSymbolAddress((void**)&bufA, g_bufA);
    cudaGetSymbolAddress((void**)&bufB, g_bufB);
    cudaGetSymbolAddress((void**)&zbuf, g_z);
    cudaGetSymbolAddress((void**)&bnInv,  g_bnInv);
    cudaGetSymbolAddress((void**)&bnBeta, g_bnBeta);

    cudaFuncSetAttribute(conv1_k,  cudaFuncAttributeMaxDynamicSharedMemorySize, SMEM_BYTES);
    cudaFuncSetAttribute(conv2_k,  cudaFuncAttributeMaxDynamicSharedMemorySize, SMEM_BYTES);
    cudaFuncSetAttribute(conv3_k,  cudaFuncAttributeMaxDynamicSharedMemorySize, SMEM_BYTES);
    cudaFuncSetAttribute(conv45_k, cudaFuncAttributeMaxDynamicSharedMemorySize, SMEM_BYTES);

    zero_k<<<1, 576>>>();
    bnprep_k<<<(5 * NC + 255) / 256, 256>>>(bng, bnb, bnm, bnv);
    e2_k<<<2, 256>>>(emb);

    // conv1: [32,80,1024] -> [32,768,1022]
    conv1_k<<<dim3((NB * T1 + 127) / 128, NC / 128), 256, SMEM_BYTES>>>(
        mels, w1, bnInv + 0 * NC, bnBeta + 0 * NC, bufA);
    // conv2
    conv2_k<<<dim3((NB * T1 + 127) / 128, NC / 128), 256, SMEM_BYTES>>>(
        bufA, w2, bnInv + 1 * NC, bnBeta + 1 * NC, bufB);
    // conv3 (stride 2): -> [32,768,511]
    conv3_k<<<dim3((NB * T2 + 127) / 128, NC / 128), 256, SMEM_BYTES>>>(
        bufB, w3, bnInv + 2 * NC, bnBeta + 2 * NC, bufA);
    // conv4
    conv45_k<<<dim3((NB * T2 + 127) / 128, NC / 128), 256, SMEM_BYTES>>>(
        bufA, w4, bnInv + 3 * NC, bnBeta + 3 * NC, bufB);
    // conv5
    conv45_k<<<dim3((NB * T2 + 127) / 128, NC / 128), 256, SMEM_BYTES>>>(
        bufB, w5, bnInv + 4 * NC, bnBeta + 4 * NC, bufA);
    // 1x1 projection + transpose -> z
    conv6_k<<<dim3((T2 + 63) / 64, NB), dim3(16, 16)>>>(bufA, w6, b6, zbuf);
    // VQ
    dist_k<<<dim3((NQ + 63) / 64, NM / 64), dim3(16, 16)>>>(emb);
    vq_k<<<NQ / 8, 256>>>(emb, out);
    finalize_k<<<1, NM>>>(out);
}

extern "C" void kernel_launch(void* const* d_in, const int* in_sizes, int n_in,
                              void* d_out, int out_size)
{
    encoder_run((const float*)d_in[0], (const float*)d_in[1], (const float*)d_in[2],
                (const float*)d_in[3], (const float*)d_in[4], (const float*)d_in[5],
                (const float*)d_in[6], (const float*)d_in[7], (const float*)d_in[8],
                (const float*)d_in[9], (const float*)d_in[10], (const float*)d_in[11],
                (const float*)d_in[12], (float*)d_out);
}

// round 9
// speedup vs baseline: 2.0279x; 2.0279x over previous
#include <cuda_runtime.h>
#include <cuda_fp16.h>
#include <cstdint>
#include <math.h>

// ---------------- problem constants ----------------
constexpr int NB   = 32;
constexpr int NC   = 768;
constexpr int CIN0 = 80;
constexpr int T0   = 1024;
constexpr int T1   = 1022;
constexpr int T2   = 511;
constexpr int ND   = 64;
constexpr int NM   = 512;
constexpr int NQ   = NB * T2;
constexpr int NQE  = NQ * ND;
constexpr float BN_EPS = 1e-5f;
constexpr float WSCALE = 1024.0f;   // weight pre-scale keeps fp16 lo out of subnormals

constexpr int KK1  = CIN0 * 3;      // 240
constexpr int KK2  = NC * 3;        // 2304
constexpr int KK3  = NC * 4;        // 3072

// smem: 2 stages x (Ah, Al, Bh, Bl), each 128 rows x 40 halves
constexpr int LDH        = 40;
constexpr int BUF_BYTES  = 4 * 128 * LDH * 2;   // 40960
constexpr int SMEM_BYTES = 2 * BUF_BYTES;       // 81920

// ---------------- scratch ----------------
__device__ uint32_t g_pmels[NB * CIN0 * T0];    // packed hi/lo mels
__device__ uint32_t g_pactA[NB * NC * T1];      // packed activations ping
__device__ uint32_t g_pactB[NB * NC * T1];      // packed activations pong
__device__ uint32_t g_pw1[NC * KK1];
__device__ uint32_t g_pw2[NC * KK2];
__device__ uint32_t g_pw3[NC * KK3];
__device__ uint32_t g_pw4[NC * KK2];
__device__ uint32_t g_pw5[NC * KK2];
__device__ float g_z[NQE];
__device__ float g_dist[NQ * NM];
__device__ float g_bnInv[5 * NC];
__device__ float g_bnBeta[5 * NC];
__device__ float g_e2[NM];
__device__ int   g_counts[NM];
__device__ float g_loss[1];

// ---------------- helpers ----------------
// fp32 -> packed (hi fp16 in low16, residual-lo fp16 in high16)
__device__ __forceinline__ uint32_t packsplit(float v) {
    __half h = __float2half_rn(v);
    float  r = v - __half2float(h);
    __half l = __float2half_rn(r);
    return (uint32_t)__half_as_ushort(h) | ((uint32_t)__half_as_ushort(l) << 16);
}
__device__ __forceinline__ float unpacksum(uint32_t u) {
    return __half2float(__ushort_as_half((unsigned short)(u & 0xffff)))
         + __half2float(__ushort_as_half((unsigned short)(u >> 16)));
}

__device__ __forceinline__ void mma16816(float* c, const uint32_t* a, const uint32_t* b) {
    asm volatile(
        "mma.sync.aligned.m16n8k16.row.col.f32.f16.f16.f32 "
        "{%0,%1,%2,%3}, {%4,%5,%6,%7}, {%8,%9}, {%0,%1,%2,%3};"
        : "+f"(c[0]), "+f"(c[1]), "+f"(c[2]), "+f"(c[3])
        : "r"(a[0]), "r"(a[1]), "r"(a[2]), "r"(a[3]), "r"(b[0]), "r"(b[1]));
}

// ---------------- tiny prep kernels ----------------
__global__ void zero_k() {
    int i = threadIdx.x;
    if (i < NM) g_counts[i] = 0;
    if (i == NM) g_loss[0] = 0.f;
}

__global__ void bnprep_k(const float* __restrict__ g, const float* __restrict__ b,
                         const float* __restrict__ m, const float* __restrict__ v) {
    int i = blockIdx.x * blockDim.x + threadIdx.x;
    if (i < 5 * NC) {
        float inv = g[i] * rsqrtf(v[i] + BN_EPS);
        g_bnInv[i]  = inv / WSCALE;
        g_bnBeta[i] = b[i] - m[i] * inv;
    }
}

__global__ void packw_k(const float* __restrict__ w, uint32_t* __restrict__ pw, int n) {
    int i = blockIdx.x * blockDim.x + threadIdx.x;
    if (i < n) pw[i] = packsplit(w[i] * WSCALE);
}

__global__ void packx_k(const float* __restrict__ x, uint32_t* __restrict__ px, int n) {
    int i = blockIdx.x * blockDim.x + threadIdx.x;
    if (i < n) px[i] = packsplit(x[i]);
}

__global__ void e2_k(const float* __restrict__ emb) {
    int e = blockIdx.x * blockDim.x + threadIdx.x;
    if (e < NM) {
        float s = 0.f;
        #pragma unroll
        for (int d = 0; d < ND; d++) { float t = emb[e * ND + d]; s += t * t; }
        g_e2[e] = s;
    }
}

// ---------------- conv1d + BN + ReLU via mma.sync, packed hi/lo fp16 ----------------
// D[m][n] = sum_kk A[m][kk]*B[n][kk];  A = packed w, B = im2col(packed x)
// 3-term: Ahi*Bhi + Ahi*Blo + Alo*Bhi, fp32 accum. Output packed hi/lo.
template<int KW, int STRIDE, int PAD, int CIN, int TIN, int TOUT>
__device__ __forceinline__
void conv_mma_body(const uint32_t* __restrict__ x, const uint32_t* __restrict__ w,
                   const float* __restrict__ inv, const float* __restrict__ bet,
                   uint32_t* __restrict__ out)
{
    constexpr int KK    = CIN * KW;
    constexpr int NS    = (KK + 31) / 32;
    constexpr int NCOLS = NB * TOUT;

    extern __shared__ char smem[];

    const int tid  = threadIdx.x;
    const int lane = tid & 31;
    const int warp = tid >> 5;
    const int gid  = lane >> 2;
    const int tig  = lane & 3;
    const int mw   = warp >> 2;     // 0..1
    const int nw   = warp & 3;      // 0..3
    const int m0 = blockIdx.y * 128;
    const int n0 = blockIdx.x * 128;

    // staging maps
    const int arow = tid >> 1;
    const int ak0  = (tid & 1) * 16;
    const int bn   = tid & 127;
    const int bk0  = (tid >> 7) * 16;
    const int ncolB = n0 + bn;
    const bool cv   = ncolB < NCOLS;
    const int nbB = cv ? (ncolB / TOUT) : 0;
    const int tB  = cv ? (ncolB - nbB * TOUT) : 0;
    const uint32_t* xrow = x + (size_t)nbB * CIN * TIN;
    const uint32_t* wrow = w + (size_t)(m0 + arow) * KK;

    uint32_t ar[16], br[16];
    float acc[4][4][4];
    #pragma unroll
    for (int a = 0; a < 4; a++)
        #pragma unroll
        for (int b = 0; b < 4; b++)
            #pragma unroll
            for (int c = 0; c < 4; c++) acc[a][b][c] = 0.f;

    auto LOADS = [&](int kt) {
        #pragma unroll
        for (int j = 0; j < 4; j++) {
            int kk = kt + ak0 + j * 4;
            if (kk + 3 < KK) {
                uint4 v = *(const uint4*)(wrow + kk);
                ar[j*4+0] = v.x; ar[j*4+1] = v.y; ar[j*4+2] = v.z; ar[j*4+3] = v.w;
            } else {
                #pragma unroll
                for (int q = 0; q < 4; q++)
                    ar[j*4+q] = (kk + q < KK) ? wrow[kk + q] : 0u;
            }
        }
        #pragma unroll
        for (int i = 0; i < 16; i++) {
            int kk = kt + bk0 + i;
            uint32_t v = 0u;
            if (cv && kk < KK) {
                int ci = kk / KW, kp = kk - ci * KW;
                int tin = tB * STRIDE + kp - PAD;
                if (tin >= 0 && tin < TIN) v = xrow[(size_t)ci * TIN + tin];
            }
            br[i] = v;
        }
    };

    auto STORES = [&](int s) {
        __half* Ah = (__half*)(smem + s * BUF_BYTES);
        __half* Al = Ah + 128 * LDH;
        __half* Bh = Al + 128 * LDH;
        __half* Bl = Bh + 128 * LDH;
        #pragma unroll
        for (int i = 0; i < 8; i++) {
            uint32_t hiA = __byte_perm(ar[2*i], ar[2*i+1], 0x5410);
            uint32_t loA = __byte_perm(ar[2*i], ar[2*i+1], 0x7632);
            *(uint32_t*)&Ah[arow * LDH + ak0 + 2*i] = hiA;
            *(uint32_t*)&Al[arow * LDH + ak0 + 2*i] = loA;
            uint32_t hiB = __byte_perm(br[2*i], br[2*i+1], 0x5410);
            uint32_t loB = __byte_perm(br[2*i], br[2*i+1], 0x7632);
            *(uint32_t*)&Bh[bn * LDH + bk0 + 2*i] = hiB;
            *(uint32_t*)&Bl[bn * LDH + bk0 + 2*i] = loB;
        }
    };

    auto COMPUTE = [&](int s) {
        const __half* Ah = (const __half*)(smem + s * BUF_BYTES);
        const __half* Al = Ah + 128 * LDH;
        const __half* Bh = Al + 128 * LDH;
        const __half* Bl = Bh + 128 * LDH;
        #pragma unroll
        for (int kh = 0; kh < 2; kh++) {
            const int k16 = kh * 16;
            uint32_t aH[4][4], aL[4][4];
            #pragma unroll
            for (int mi = 0; mi < 4; mi++) {
                int r = mw * 64 + mi * 16 + gid;
                aH[mi][0] = *(const uint32_t*)&Ah[ r      * LDH + k16 + 2*tig    ];
                aH[mi][1] = *(const uint32_t*)&Ah[(r + 8) * LDH + k16 + 2*tig    ];
                aH[mi][2] = *(const uint32_t*)&Ah[ r      * LDH + k16 + 2*tig + 8];
                aH[mi][3] = *(const uint32_t*)&Ah[(r + 8) * LDH + k16 + 2*tig + 8];
                aL[mi][0] = *(const uint32_t*)&Al[ r      * LDH + k16 + 2*tig    ];
                aL[mi][1] = *(const uint32_t*)&Al[(r + 8) * LDH + k16 + 2*tig    ];
                aL[mi][2] = *(const uint32_t*)&Al[ r      * LDH + k16 + 2*tig + 8];
                aL[mi][3] = *(const uint32_t*)&Al[(r + 8) * LDH + k16 + 2*tig + 8];
            }
            #pragma unroll
            for (int ni = 0; ni < 4; ni++) {
                int n = nw * 32 + ni * 8 + gid;
                uint32_t bH[2], bL[2];
                bH[0] = *(const uint32_t*)&Bh[n * LDH + k16 + 2*tig    ];
                bH[1] = *(const uint32_t*)&Bh[n * LDH + k16 + 2*tig + 8];
                bL[0] = *(const uint32_t*)&Bl[n * LDH + k16 + 2*tig    ];
                bL[1] = *(const uint32_t*)&Bl[n * LDH + k16 + 2*tig + 8];
                #pragma unroll
                for (int mi = 0; mi < 4; mi++) {
                    mma16816(acc[mi][ni], aH[mi], bH);
                    mma16816(acc[mi][ni], aH[mi], bL);
                    mma16816(acc[mi][ni], aL[mi], bH);
                }
            }
        }
    };

    LOADS(0);
    STORES(0);
    __syncthreads();
    for (int s = 0; s < NS; s++) {
        if (s + 1 < NS) {
            LOADS((s + 1) * 32);
            STORES((s + 1) & 1);       // staging regs dead during COMPUTE
        }
        COMPUTE(s & 1);
        __syncthreads();
    }

    // epilogue: BN + ReLU, split-pack, store
    #pragma unroll
    for (int mi = 0; mi < 4; mi++) {
        int r1 = m0 + mw * 64 + mi * 16 + gid;
        int r2 = r1 + 8;
        float iv1 = inv[r1], bb1 = bet[r1];
        float iv2 = inv[r2], bb2 = bet[r2];
        #pragma unroll
        for (int ni = 0; ni < 4; ni++) {
            int nc = n0 + nw * 32 + ni * 8 + 2 * tig;
            #pragma unroll
            for (int q = 0; q < 2; q++) {
                int ncol = nc + q;
                if (ncol < NCOLS) {
                    int nb = ncol / TOUT, t = ncol - nb * TOUT;
                    float v1 = acc[mi][ni][q]     * iv1 + bb1;
                    float v2 = acc[mi][ni][2 + q] * iv2 + bb2;
                    out[((size_t)nb * NC + r1) * TOUT + t] = packsplit(v1 > 0.f ? v1 : 0.f);
                    out[((size_t)nb * NC + r2) * TOUT + t] = packsplit(v2 > 0.f ? v2 : 0.f);
                }
            }
        }
    }
}

// ---- non-template global wrappers ----
__global__ __launch_bounds__(256, 2)
void conv1_k(const uint32_t* __restrict__ x, const uint32_t* __restrict__ w,
             const float* __restrict__ inv, const float* __restrict__ bet,
             uint32_t* __restrict__ out) {
    conv_mma_body<3, 1, 0, CIN0, T0, T1>(x, w, inv, bet, out);
}
__global__ __launch_bounds__(256, 2)
void conv2_k(const uint32_t* __restrict__ x, const uint32_t* __restrict__ w,
             const float* __restrict__ inv, const float* __restrict__ bet,
             uint32_t* __restrict__ out) {
    conv_mma_body<3, 1, 1, NC, T1, T1>(x, w, inv, bet, out);
}
__global__ __launch_bounds__(256, 2)
void conv3_k(const uint32_t* __restrict__ x, const uint32_t* __restrict__ w,
             const float* __restrict__ inv, const float* __restrict__ bet,
             uint32_t* __restrict__ out) {
    conv_mma_body<4, 2, 1, NC, T1, T2>(x, w, inv, bet, out);
}
__global__ __launch_bounds__(256, 2)
void conv45_k(const uint32_t* __restrict__ x, const uint32_t* __restrict__ w,
              const float* __restrict__ inv, const float* __restrict__ bet,
              uint32_t* __restrict__ out) {
    conv_mma_body<3, 1, 1, NC, T2, T2>(x, w, inv, bet, out);
}

// ---------------- 1x1 projection + bias + transpose to [B, T', D] (fp32) ----------------
__global__ __launch_bounds__(256)
void conv6_k(const uint32_t* __restrict__ x, const float* __restrict__ w6,
             const float* __restrict__ b6, float* __restrict__ z)
{
    __shared__ float Xs[16][64];
    __shared__ float Ws[16][65];
    const int tx = threadIdx.x, ty = threadIdx.y;
    const int tid = ty * 16 + tx;
    const int t0 = blockIdx.x * 64;
    const int b  = blockIdx.y;

    float acc[4][4] = {};
    for (int c0 = 0; c0 < NC; c0 += 16) {
        #pragma unroll
        for (int j = 0; j < 4; j++) {
            int idx = tid + j * 256;
            int tl = idx & 63, kk = idx >> 6;
            int t = t0 + tl;
            Xs[kk][tl] = (t < T2) ? unpacksum(x[((size_t)b * NC + c0 + kk) * T2 + t]) : 0.f;
        }
        #pragma unroll
        for (int j = 0; j < 4; j++) {
            int idx = tid + j * 256;
            int dl = idx & 63, kk = idx >> 6;
            Ws[kk][dl] = w6[dl * NC + c0 + kk];
        }
        __syncthreads();
        #pragma unroll
        for (int k = 0; k < 16; k++) {
            float a[4], wv[4];
            #pragma unroll
            for (int i = 0; i < 4; i++) a[i] = Xs[k][ty * 4 + i];
            #pragma unroll
            for (int j = 0; j < 4; j++) wv[j] = Ws[k][tx * 4 + j];
            #pragma unroll
            for (int i = 0; i < 4; i++)
                #pragma unroll
                for (int j = 0; j < 4; j++)
                    acc[i][j] = fmaf(a[i], wv[j], acc[i][j]);
        }
        __syncthreads();
    }
    #pragma unroll
    for (int i = 0; i < 4; i++) {
        int t = t0 + ty * 4 + i;
        if (t < T2) {
            #pragma unroll
            for (int j = 0; j < 4; j++) {
                int d = tx * 4 + j;
                z[((size_t)b * T2 + t) * ND + d] = acc[i][j] + b6[d];
            }
        }
    }
}

// ---------------- VQ distance GEMM (fp32) ----------------
__global__ __launch_bounds__(256)
void dist_k(const float* __restrict__ emb)
{
    __shared__ float zs[64][65];
    __shared__ float es[64][65];
    const int tx = threadIdx.x, ty = threadIdx.y;
    const int tid = ty * 16 + tx;
    const int row0 = blockIdx.x * 64;
    const int e0   = blockIdx.y * 64;

    #pragma unroll
    for (int j = 0; j < 16; j++) {
        int idx = tid + j * 256;
        int k = idx & 63, r = idx >> 6;
        zs[r][k] = (row0 + r < NQ) ? g_z[(size_t)(row0 + r) * ND + k] : 0.f;
    }
    #pragma unroll
    for (int j = 0; j < 16; j++) {
        int idx = tid + j * 256;
        int k = idx & 63, e = idx >> 6;
        es[e][k] = emb[(size_t)(e0 + e) * ND + k];
    }
    __syncthreads();

    float acc[4][4] = {};
    #pragma unroll
    for (int k = 0; k < 64; k++) {
        float a[4], b[4];
        #pragma unroll
        for (int i = 0; i < 4; i++) a[i] = zs[ty * 4 + i][k];
        #pragma unroll
        for (int j = 0; j < 4; j++) b[j] = es[tx * 4 + j][k];
        #pragma unroll
        for (int i = 0; i < 4; i++)
            #pragma unroll
            for (int j = 0; j < 4; j++)
                acc[i][j] = fmaf(a[i], b[j], acc[i][j]);
    }

    #pragma unroll
    for (int i = 0; i < 4; i++) {
        int row = row0 + ty * 4 + i;
        if (row < NQ) {
            #pragma unroll
            for (int j = 0; j < 4; j++) {
                int e = e0 + tx * 4 + j;
                g_dist[(size_t)row * NM + e] = g_e2[e] - 2.f * acc[i][j];
            }
        }
    }
}

// ---------------- argmin + quantize + loss + counts ----------------
__global__ __launch_bounds__(256)
void vq_k(const float* __restrict__ emb, float* __restrict__ out_q)
{
    const int warp = threadIdx.x >> 5;
    const int lane = threadIdx.x & 31;
    const int row = blockIdx.x * 8 + warp;
    const float* dr = g_dist + (size_t)row * NM;

    float best = 3.4e38f; int bi = NM;
    #pragma unroll
    for (int i = 0; i < 16; i++) {
        int e = i * 32 + lane;
        float v = dr[e];
        if (v < best) { best = v; bi = e; }
    }
    #pragma unroll
    for (int off = 16; off > 0; off >>= 1) {
        float ob = __shfl_down_sync(0xffffffffu, best, off);
        int   oi = __shfl_down_sync(0xffffffffu, bi,   off);
        if (ob < best || (ob == best && oi < bi)) { best = ob; bi = oi; }
    }
    bi = __shfl_sync(0xffffffffu, bi, 0);

    const float* zr = g_z + (size_t)row * ND;
    const float* er = emb + (size_t)bi * ND;
    float lsum = 0.f;
    #pragma unroll
    for (int d0 = 0; d0 < ND; d0 += 32) {
        int d = d0 + lane;
        float zv = zr[d], qv = er[d];
        out_q[(size_t)row * ND + d] = zv + (qv - zv);
        float df = zv - qv;
        lsum += df * df;
    }
    #pragma unroll
    for (int off = 16; off > 0; off >>= 1)
        lsum += __shfl_down_sync(0xffffffffu, lsum, off);
    if (lane == 0) {
        atomicAdd(&g_loss[0], lsum);
        atomicAdd(&g_counts[bi], 1);
    }
}

__global__ void finalize_k(float* __restrict__ out)
{
    __shared__ float sh[NM];
    int tid = threadIdx.x;
    float p = (float)g_counts[tid] / (float)NQ;
    sh[tid] = -p * logf(p + 1e-10f);
    __syncthreads();
    for (int s = NM / 2; s > 0; s >>= 1) {
        if (tid < s) sh[tid] += sh[tid + s];
        __syncthreads();
    }
    if (tid == 0) {
        out[NQE]     = 0.25f * g_loss[0] / (float)NQE;
        out[NQE + 1] = expf(sh[0]);
    }
}

// ---------------- host-side driver ----------------
static void encoder_run(const float* mels, const float* w1, const float* w2,
                        const float* w3, const float* w4, const float* w5,
                        const float* w6, const float* b6,
                        const float* bng, const float* bnb,
                        const float* bnm, const float* bnv,
                        const float* emb, float* out)
{
    uint32_t *pmels, *pactA, *pactB, *pw1, *pw2, *pw3, *pw4, *pw5;
    float *zbuf, *bnInv, *bnBeta;
    cudaGetSymbolAddress((void**)&pmels, g_pmels);
    cudaGetSymbolAddress((void**)&pactA, g_pactA);
    cudaGetSymbolAddress((void**)&pactB, g_pactB);
    cudaGetSymbolAddress((void**)&pw1, g_pw1);
    cudaGetSymbolAddress((void**)&pw2, g_pw2);
    cudaGetSymbolAddress((void**)&pw3, g_pw3);
    cudaGetSymbolAddress((void**)&pw4, g_pw4);
    cudaGetSymbolAddress((void**)&pw5, g_pw5);
    cudaGetSymbolAddress((void**)&zbuf, g_z);
    cudaGetSymbolAddress((void**)&bnInv,  g_bnInv);
    cudaGetSymbolAddress((void**)&bnBeta, g_bnBeta);

    cudaFuncSetAttribute(conv1_k,  cudaFuncAttributeMaxDynamicSharedMemorySize, SMEM_BYTES);
    cudaFuncSetAttribute(conv2_k,  cudaFuncAttributeMaxDynamicSharedMemorySize, SMEM_BYTES);
    cudaFuncSetAttribute(conv3_k,  cudaFuncAttributeMaxDynamicSharedMemorySize, SMEM_BYTES);
    cudaFuncSetAttribute(conv45_k, cudaFuncAttributeMaxDynamicSharedMemorySize, SMEM_BYTES);

    zero_k<<<1, 576>>>();
    bnprep_k<<<(5 * NC + 255) / 256, 256>>>(bng, bnb, bnm, bnv);
    e2_k<<<2, 256>>>(emb);
    packw_k<<<(NC * KK1 + 255) / 256, 256>>>(w1, pw1, NC * KK1);
    packw_k<<<(NC * KK2 + 255) / 256, 256>>>(w2, pw2, NC * KK2);
    packw_k<<<(NC * KK3 + 255) / 256, 256>>>(w3, pw3, NC * KK3);
    packw_k<<<(NC * KK2 + 255) / 256, 256>>>(w4, pw4, NC * KK2);
    packw_k<<<(NC * KK2 + 255) / 256, 256>>>(w5, pw5, NC * KK2);
    packx_k<<<(NB * CIN0 * T0 + 255) / 256, 256>>>(mels, pmels, NB * CIN0 * T0);

    // conv1: [32,80,1024] -> [32,768,1022]
    conv1_k<<<dim3((NB * T1 + 127) / 128, NC / 128), 256, SMEM_BYTES>>>(
        pmels, pw1, bnInv + 0 * NC, bnBeta + 0 * NC, pactA);
    // conv2
    conv2_k<<<dim3((NB * T1 + 127) / 128, NC / 128), 256, SMEM_BYTES>>>(
        pactA, pw2, bnInv + 1 * NC, bnBeta + 1 * NC, pactB);
    // conv3 (stride 2): -> [32,768,511]
    conv3_k<<<dim3((NB * T2 + 127) / 128, NC / 128), 256, SMEM_BYTES>>>(
        pactB, pw3, bnInv + 2 * NC, bnBeta + 2 * NC, pactA);
    // conv4
    conv45_k<<<dim3((NB * T2 + 127) / 128, NC / 128), 256, SMEM_BYTES>>>(
        pactA, pw4, bnInv + 3 * NC, bnBeta + 3 * NC, pactB);
    // conv5
    conv45_k<<<dim3((NB * T2 + 127) / 128, NC / 128), 256, SMEM_BYTES>>>(
        pactB, pw5, bnInv + 4 * NC, bnBeta + 4 * NC, pactA);
    // 1x1 projection + transpose -> z
    conv6_k<<<dim3((T2 + 63) / 64, NB), dim3(16, 16)>>>(pactA, w6, b6, zbuf);
    // VQ
    dist_k<<<dim3((NQ + 63) / 64, NM / 64), dim3(16, 16)>>>(emb);
    vq_k<<<NQ / 8, 256>>>(emb, out);
    finalize_k<<<1, NM>>>(out);
}

extern "C" void kernel_launch(void* const* d_in, const int* in_sizes, int n_in,
                              void* d_out, int out_size)
{
    encoder_run((const float*)d_in[0], (const float*)d_in[1], (const float*)d_in[2],
                (const float*)d_in[3], (const float*)d_in[4], (const float*)d_in[5],
                (const float*)d_in[6], (const float*)d_in[7], (const float*)d_in[8],
                (const float*)d_in[9], (const float*)d_in[10], (const float*)d_in[11],
                (const float*)d_in[12], (float*)d_out);
}

// round 11
// speedup vs baseline: 2.0850x; 1.0281x over previous
#include <cuda_runtime.h>
#include <cuda_fp16.h>
#include <cstdint>
#include <math.h>

// ---------------- problem constants ----------------
constexpr int NB   = 32;
constexpr int NC   = 768;
constexpr int CIN0 = 80;
constexpr int T0   = 1024;
constexpr int T1   = 1022;
constexpr int T2   = 511;
constexpr int ND   = 64;
constexpr int NM   = 512;
constexpr int NQ   = NB * T2;
constexpr int NQE  = NQ * ND;
constexpr float BN_EPS = 1e-5f;
constexpr float WSCALE = 1024.0f;

constexpr int KK1 = CIN0 * 3;     // 240  (conv1, k = ci*KW+kp order)
constexpr int KK2 = NC * 3;       // 2304 (k = kp*CIN+ci order)
constexpr int KK3 = NC * 4;       // 3072

constexpr int LDH      = 40;                  // halves per smem row (80B, 16B-aligned)
constexpr int PLANE_B  = 128 * LDH * 2;       // 10240
constexpr int STAGE_B  = 4 * PLANE_B;         // 40960 (Ah, Al, Bh, Bl)
constexpr int SMEM_BYTES = 2 * STAGE_B;       // 81920

// ---------------- scratch ----------------
__device__ uint32_t g_pmels[NB * CIN0 * T0];          // packed hi/lo mels [b][ci][t]
__device__ uint32_t g_pw1[NC * KK1];                  // packed conv1 weights
__device__ __half g_pA_h[NB * T1 * NC];               // activation planes ping [b][t][c]
__device__ __half g_pA_l[NB * T1 * NC];
__device__ __half g_pB_h[NB * T1 * NC];               // pong
__device__ __half g_pB_l[NB * T1 * NC];
__device__ __half g_w2h[NC * KK2], g_w2l[NC * KK2];
__device__ __half g_w3h[NC * KK3], g_w3l[NC * KK3];
__device__ __half g_w4h[NC * KK2], g_w4l[NC * KK2];
__device__ __half g_w5h[NC * KK2], g_w5l[NC * KK2];
__device__ float g_z[NQE];
__device__ float g_dist[NQ * NM];
__device__ float g_bnInv[5 * NC];
__device__ float g_bnBeta[5 * NC];
__device__ float g_e2[NM];
__device__ int   g_counts[NM];
__device__ float g_loss[1];

// ---------------- helpers ----------------
__device__ __forceinline__ uint32_t packsplit(float v) {
    __half h = __float2half_rn(v);
    float  r = v - __half2float(h);
    __half l = __float2half_rn(r);
    return (uint32_t)__half_as_ushort(h) | ((uint32_t)__half_as_ushort(l) << 16);
}

__device__ __forceinline__ void mma16816(float* c, const uint32_t* a, const uint32_t* b) {
    asm volatile(
        "mma.sync.aligned.m16n8k16.row.col.f32.f16.f16.f32 "
        "{%0,%1,%2,%3}, {%4,%5,%6,%7}, {%8,%9}, {%0,%1,%2,%3};"
        : "+f"(c[0]), "+f"(c[1]), "+f"(c[2]), "+f"(c[3])
        : "r"(a[0]), "r"(a[1]), "r"(a[2]), "r"(a[3]), "r"(b[0]), "r"(b[1]));
}

__device__ __forceinline__ void cpa16(uint32_t d, const void* s, int sz) {
    asm volatile("cp.async.cg.shared.global [%0], [%1], 16, %2;"
                 :: "r"(d), "l"(s), "r"(sz) : "memory");
}
__device__ __forceinline__ void cp_commit() {
    asm volatile("cp.async.commit_group;" ::: "memory");
}
__device__ __forceinline__ void cp_wait1() {
    asm volatile("cp.async.wait_group 1;" ::: "memory");
}
__device__ __forceinline__ void cp_wait0() {
    asm volatile("cp.async.wait_group 0;" ::: "memory");
}

__device__ __forceinline__ void ldsm_x4(uint32_t* r, uint32_t a) {
    asm volatile("ldmatrix.sync.aligned.m8n8.x4.shared.b16 {%0,%1,%2,%3}, [%4];"
                 : "=r"(r[0]), "=r"(r[1]), "=r"(r[2]), "=r"(r[3]) : "r"(a));
}
__device__ __forceinline__ void ldsm_x2(uint32_t* r, uint32_t a) {
    asm volatile("ldmatrix.sync.aligned.m8n8.x2.shared.b16 {%0,%1}, [%2];"
                 : "=r"(r[0]), "=r"(r[1]) : "r"(a));
}

// ---------------- tiny prep kernels ----------------
__global__ void zero_k() {
    int i = threadIdx.x;
    if (i < NM) g_counts[i] = 0;
    if (i == NM) g_loss[0] = 0.f;
}

__global__ void bnprep_k(const float* __restrict__ g, const float* __restrict__ b,
                         const float* __restrict__ m, const float* __restrict__ v) {
    int i = blockIdx.x * blockDim.x + threadIdx.x;
    if (i < 5 * NC) {
        float inv = g[i] * rsqrtf(v[i] + BN_EPS);
        g_bnInv[i]  = inv / WSCALE;
        g_bnBeta[i] = b[i] - m[i] * inv;
    }
}

__global__ void packw_k(const float* __restrict__ w, uint32_t* __restrict__ pw, int n) {
    int i = blockIdx.x * blockDim.x + threadIdx.x;
    if (i < n) pw[i] = packsplit(w[i] * WSCALE);
}

__global__ void packx_k(const float* __restrict__ x, uint32_t* __restrict__ px, int n) {
    int i = blockIdx.x * blockDim.x + threadIdx.x;
    if (i < n) px[i] = packsplit(x[i]);
}

// reorder weights to k = kp*CIN+ci, split into hi/lo planes, scale by WSCALE
__global__ void packwpl_k(const float* __restrict__ w, __half* __restrict__ wh,
                          __half* __restrict__ wl, int KW_) {
    int i = blockIdx.x * blockDim.x + threadIdx.x;
    int KKt = NC * KW_;
    if (i < NC * KKt) {
        int m = i / KKt;
        int k = i - m * KKt;
        int kp = k / NC;
        int ci = k - kp * NC;
        float v = w[(size_t)m * KKt + ci * KW_ + kp] * WSCALE;
        __half h = __float2half_rn(v);
        wh[i] = h;
        wl[i] = __float2half_rn(v - __half2float(h));
    }
}

__global__ void e2_k(const float* __restrict__ emb) {
    int e = blockIdx.x * blockDim.x + threadIdx.x;
    if (e < NM) {
        float s = 0.f;
        #pragma unroll
        for (int d = 0; d < ND; d++) { float t = emb[e * ND + d]; s += t * t; }
        g_e2[e] = s;
    }
}

// ================= conv1 (CIN=80): round-9 style, writes channel-last planes ==========
__global__ __launch_bounds__(256, 2)
void conv1_k(const uint32_t* __restrict__ x, const uint32_t* __restrict__ w,
             const float* __restrict__ inv, const float* __restrict__ bet,
             __half* __restrict__ oh, __half* __restrict__ ol)
{
    constexpr int KW = 3, STRIDE = 1, PAD = 0, CIN = CIN0, TIN = T0, TOUT = T1;
    constexpr int KK = CIN * KW;
    constexpr int NS = (KK + 31) / 32;
    constexpr int NCOLS = NB * TOUT;

    extern __shared__ char smem[];
    const int tid  = threadIdx.x;
    const int lane = tid & 31;
    const int warp = tid >> 5;
    const int gid  = lane >> 2;
    const int tig  = lane & 3;
    const int mw   = warp >> 2;
    const int nw   = warp & 3;
    const int m0 = blockIdx.y * 128;
    const int n0 = blockIdx.x * 128;

    const int arow = tid >> 1;
    const int ak0  = (tid & 1) * 16;
    const int bn   = tid & 127;
    const int bk0  = (tid >> 7) * 16;
    const int ncolB = n0 + bn;
    const bool cv   = ncolB < NCOLS;
    const int nbB = cv ? (ncolB / TOUT) : 0;
    const int tB  = cv ? (ncolB - nbB * TOUT) : 0;
    const uint32_t* xrow = x + (size_t)nbB * CIN * TIN;
    const uint32_t* wrow = w + (size_t)(m0 + arow) * KK;

    uint32_t ar[16], br[16];
    float acc[4][4][4];
    #pragma unroll
    for (int a = 0; a < 4; a++)
        #pragma unroll
        for (int b = 0; b < 4; b++)
            #pragma unroll
            for (int c = 0; c < 4; c++) acc[a][b][c] = 0.f;

    auto LOADS = [&](int kt) {
        #pragma unroll
        for (int j = 0; j < 4; j++) {
            int kk = kt + ak0 + j * 4;
            #pragma unroll
            for (int q = 0; q < 4; q++)
                ar[j*4+q] = (kk + q < KK) ? wrow[kk + q] : 0u;
        }
        #pragma unroll
        for (int i = 0; i < 16; i++) {
            int kk = kt + bk0 + i;
            uint32_t v = 0u;
            if (cv && kk < KK) {
                int ci = kk / KW, kp = kk - ci * KW;
                int tin = tB * STRIDE + kp - PAD;
                if (tin >= 0 && tin < TIN) v = xrow[(size_t)ci * TIN + tin];
            }
            br[i] = v;
        }
    };

    auto STORES = [&](int s) {
        __half* Ah = (__half*)(smem + s * STAGE_B);
        __half* Al = Ah + 128 * LDH;
        __half* Bh = Al + 128 * LDH;
        __half* Bl = Bh + 128 * LDH;
        #pragma unroll
        for (int i = 0; i < 8; i++) {
            uint32_t hiA = __byte_perm(ar[2*i], ar[2*i+1], 0x5410);
            uint32_t loA = __byte_perm(ar[2*i], ar[2*i+1], 0x7632);
            *(uint32_t*)&Ah[arow * LDH + ak0 + 2*i] = hiA;
            *(uint32_t*)&Al[arow * LDH + ak0 + 2*i] = loA;
            uint32_t hiB = __byte_perm(br[2*i], br[2*i+1], 0x5410);
            uint32_t loB = __byte_perm(br[2*i], br[2*i+1], 0x7632);
            *(uint32_t*)&Bh[bn * LDH + bk0 + 2*i] = hiB;
            *(uint32_t*)&Bl[bn * LDH + bk0 + 2*i] = loB;
        }
    };

    auto COMPUTE = [&](int s) {
        const __half* Ah = (const __half*)(smem + s * STAGE_B);
        const __half* Al = Ah + 128 * LDH;
        const __half* Bh = Al + 128 * LDH;
        const __half* Bl = Bh + 128 * LDH;
        #pragma unroll
        for (int kh = 0; kh < 2; kh++) {
            const int k16 = kh * 16;
            uint32_t aH[4][4], aL[4][4];
            #pragma unroll
            for (int mi = 0; mi < 4; mi++) {
                int r = mw * 64 + mi * 16 + gid;
                aH[mi][0] = *(const uint32_t*)&Ah[ r      * LDH + k16 + 2*tig    ];
                aH[mi][1] = *(const uint32_t*)&Ah[(r + 8) * LDH + k16 + 2*tig    ];
                aH[mi][2] = *(const uint32_t*)&Ah[ r      * LDH + k16 + 2*tig + 8];
                aH[mi][3] = *(const uint32_t*)&Ah[(r + 8) * LDH + k16 + 2*tig + 8];
                aL[mi][0] = *(const uint32_t*)&Al[ r      * LDH + k16 + 2*tig    ];
                aL[mi][1] = *(const uint32_t*)&Al[(r + 8) * LDH + k16 + 2*tig    ];
                aL[mi][2] = *(const uint32_t*)&Al[ r      * LDH + k16 + 2*tig + 8];
                aL[mi][3] = *(const uint32_t*)&Al[(r + 8) * LDH + k16 + 2*tig + 8];
            }
            #pragma unroll
            for (int ni = 0; ni < 4; ni++) {
                int n = nw * 32 + ni * 8 + gid;
                uint32_t bH[2], bL[2];
                bH[0] = *(const uint32_t*)&Bh[n * LDH + k16 + 2*tig    ];
                bH[1] = *(const uint32_t*)&Bh[n * LDH + k16 + 2*tig + 8];
                bL[0] = *(const uint32_t*)&Bl[n * LDH + k16 + 2*tig    ];
                bL[1] = *(const uint32_t*)&Bl[n * LDH + k16 + 2*tig + 8];
                #pragma unroll
                for (int mi = 0; mi < 4; mi++) {
                    mma16816(acc[mi][ni], aH[mi], bH);
                    mma16816(acc[mi][ni], aH[mi], bL);
                    mma16816(acc[mi][ni], aL[mi], bH);
                }
            }
        }
    };

    LOADS(0);
    STORES(0);
    __syncthreads();
    for (int s = 0; s < NS; s++) {
        if (s + 1 < NS) {
            LOADS((s + 1) * 32);
            STORES((s + 1) & 1);
        }
        COMPUTE(s & 1);
        __syncthreads();
    }

    // epilogue: BN+ReLU -> channel-last hi/lo planes
    #pragma unroll
    for (int mi = 0; mi < 4; mi++) {
        int r1 = m0 + mw * 64 + mi * 16 + gid;
        int r2 = r1 + 8;
        float iv1 = inv[r1], bb1 = bet[r1];
        float iv2 = inv[r2], bb2 = bet[r2];
        #pragma unroll
        for (int ni = 0; ni < 4; ni++) {
            int nc = n0 + nw * 32 + ni * 8 + 2 * tig;
            #pragma unroll
            for (int q = 0; q < 2; q++) {
                int ncol = nc + q;
                if (ncol < NCOLS) {
                    float v1 = acc[mi][ni][q]     * iv1 + bb1;
                    float v2 = acc[mi][ni][2 + q] * iv2 + bb2;
                    v1 = v1 > 0.f ? v1 : 0.f;
                    v2 = v2 > 0.f ? v2 : 0.f;
                    size_t base = (size_t)ncol * NC;   // ncol = b*TOUT+t
                    __half h1 = __float2half_rn(v1);
                    __half h2 = __float2half_rn(v2);
                    oh[base + r1] = h1;
                    ol[base + r1] = __float2half_rn(v1 - __half2float(h1));
                    oh[base + r2] = h2;
                    ol[base + r2] = __float2half_rn(v2 - __half2float(h2));
                }
            }
        }
    }
}

// ===== convs 2-5: channel-last planes, cp.async staging + ldmatrix fragments =====
template<int KW, int STRIDE, int PAD, int TIN, int TOUT>
__device__ __forceinline__
void conv_cl_body(const __half* __restrict__ xh, const __half* __restrict__ xl,
                  const __half* __restrict__ wh, const __half* __restrict__ wl,
                  const float* __restrict__ inv, const float* __restrict__ bet,
                  __half* __restrict__ oh, __half* __restrict__ ol)
{
    constexpr int CIN = NC;
    constexpr int KK  = CIN * KW;
    constexpr int NS  = KK / 32;
    constexpr int NCOLS = NB * TOUT;

    extern __shared__ char smem[];
    const uint32_t sbase = (uint32_t)__cvta_generic_to_shared(smem);

    const int tid  = threadIdx.x;
    const int lane = tid & 31;
    const int warp = tid >> 5;
    const int gid  = lane >> 2;
    const int tig  = lane & 3;
    const int mw   = warp >> 2;
    const int nw   = warp & 3;
    const int m0 = blockIdx.y * 128;
    const int n0 = blockIdx.x * 128;

    // cp.async task: tid<128 -> A row; tid>=128 -> B row
    const int rrow = tid & 127;
    const bool isA = tid < 128;
    const int ncolB = n0 + rrow;
    const bool cvB  = ncolB < NCOLS;
    const int nbB = cvB ? (ncolB / TOUT) : 0;
    const int tB  = cvB ? (ncolB - nbB * TOUT) : 0;
    const __half* wrh = wh + (size_t)(m0 + rrow) * KK;
    const __half* wrl = wl + (size_t)(m0 + rrow) * KK;
    const uint32_t dst_h0 = sbase + (isA ? 0 : 2 * PLANE_B) + rrow * (LDH * 2);
    const uint32_t dst_l0 = dst_h0 + PLANE_B;

    float acc[4][4][4];
    #pragma unroll
    for (int a = 0; a < 4; a++)
        #pragma unroll
        for (int b = 0; b < 4; b++)
            #pragma unroll
            for (int c = 0; c < 4; c++) acc[a][b][c] = 0.f;

    auto ISSUE = [&](int s) {
        const int kt = s * 32;
        const uint32_t dh = dst_h0 + (s & 1) * STAGE_B;
        const uint32_t dl = dst_l0 + (s & 1) * STAGE_B;
        if (isA) {
            const __half* sh = wrh + kt;
            const __half* sl = wrl + kt;
            #pragma unroll
            for (int c = 0; c < 4; c++) {
                cpa16(dh + c * 16, sh + c * 8, 16);
                cpa16(dl + c * 16, sl + c * 8, 16);
            }
        } else {
            int kp  = kt / CIN;
            int ci0 = kt - kp * CIN;
            int tin = tB * STRIDE + kp - PAD;
            bool ok = cvB && tin >= 0 && tin < TIN;
            int tin_c = ok ? tin : 0;
            const __half* sh = xh + ((size_t)nbB * TIN + tin_c) * CIN + ci0;
            const __half* sl = xl + ((size_t)nbB * TIN + tin_c) * CIN + ci0;
            int sz = ok ? 16 : 0;
            #pragma unroll
            for (int c = 0; c < 4; c++) {
                cpa16(dh + c * 16, sh + c * 8, sz);
                cpa16(dl + c * 16, sl + c * 8, sz);
            }
        }
        cp_commit();
    };

    // ldmatrix lane address components
    const int lrowA = lane & 15;
    const int lcolA = (lane >> 4) * 8;
    const int lrowB = lane & 7;
    const int lcolB = (lane & 8) ? 8 : 0;

    auto COMPUTE = [&](int st) {
        const uint32_t pAh = sbase + st * STAGE_B;
        const uint32_t pAl = pAh + PLANE_B;
        const uint32_t pBh = pAh + 2 * PLANE_B;
        const uint32_t pBl = pAh + 3 * PLANE_B;
        #pragma unroll
        for (int kh = 0; kh < 2; kh++) {
            const int k16 = kh * 16;
            uint32_t bH[4][2], bL[4][2];
            #pragma unroll
            for (int ni = 0; ni < 4; ni++) {
                uint32_t off = ((nw * 32 + ni * 8 + lrowB) * LDH + k16 + lcolB) * 2;
                ldsm_x2(bH[ni], pBh + off);
                ldsm_x2(bL[ni], pBl + off);
            }
            #pragma unroll
            for (int mi = 0; mi < 4; mi++) {
                uint32_t off = ((mw * 64 + mi * 16 + lrowA) * LDH + k16 + lcolA) * 2;
                uint32_t aH[4], aL[4];
                ldsm_x4(aH, pAh + off);
                ldsm_x4(aL, pAl + off);
                #pragma unroll
                for (int ni = 0; ni < 4; ni++) {
                    mma16816(acc[mi][ni], aH, bH[ni]);
                    mma16816(acc[mi][ni], aH, bL[ni]);
                    mma16816(acc[mi][ni], aL, bH[ni]);
                }
            }
        }
    };

    ISSUE(0);
    for (int s = 0; s < NS; s++) {
        if (s + 1 < NS) { ISSUE(s + 1); cp_wait1(); }
        else            { cp_wait0(); }
        __syncthreads();
        COMPUTE(s & 1);
        __syncthreads();
    }

    // epilogue: BN+ReLU -> channel-last hi/lo planes
    #pragma unroll
    for (int mi = 0; mi < 4; mi++) {
        int r1 = m0 + mw * 64 + mi * 16 + gid;
        int r2 = r1 + 8;
        float iv1 = inv[r1], bb1 = bet[r1];
        float iv2 = inv[r2], bb2 = bet[r2];
        #pragma unroll
        for (int ni = 0; ni < 4; ni++) {
            int nc = n0 + nw * 32 + ni * 8 + 2 * tig;
            #pragma unroll
            for (int q = 0; q < 2; q++) {
                int ncol = nc + q;
                if (ncol < NCOLS) {
                    float v1 = acc[mi][ni][q]     * iv1 + bb1;
                    float v2 = acc[mi][ni][2 + q] * iv2 + bb2;
                    v1 = v1 > 0.f ? v1 : 0.f;
                    v2 = v2 > 0.f ? v2 : 0.f;
                    size_t base = (size_t)ncol * NC;
                    __half h1 = __float2half_rn(v1);
                    __half h2 = __float2half_rn(v2);
                    oh[base + r1] = h1;
                    ol[base + r1] = __float2half_rn(v1 - __half2float(h1));
                    oh[base + r2] = h2;
                    ol[base + r2] = __float2half_rn(v2 - __half2float(h2));
                }
            }
        }
    }
}

__global__ __launch_bounds__(256, 2)
void conv2_k(const __half* xh, const __half* xl, const __half* wh, const __half* wl,
             const float* inv, const float* bet, __half* oh, __half* ol) {
    conv_cl_body<3, 1, 1, T1, T1>(xh, xl, wh, wl, inv, bet, oh, ol);
}
__global__ __launch_bounds__(256, 2)
void conv3_k(const __half* xh, const __half* xl, const __half* wh, const __half* wl,
             const float* inv, const float* bet, __half* oh, __half* ol) {
    conv_cl_body<4, 2, 1, T1, T2>(xh, xl, wh, wl, inv, bet, oh, ol);
}
__global__ __launch_bounds__(256, 2)
void conv45_k(const __half* xh, const __half* xl, const __half* wh, const __half* wl,
              const float* inv, const float* bet, __half* oh, __half* ol) {
    conv_cl_body<3, 1, 1, T2, T2>(xh, xl, wh, wl, inv, bet, oh, ol);
}

// ---------------- 1x1 projection + bias -> z [B, T', D] (channel-last input) ----------
__global__ __launch_bounds__(256)
void conv6_k(const __half* __restrict__ xh, const __half* __restrict__ xl,
             const float* __restrict__ w6, const float* __restrict__ b6,
             float* __restrict__ z)
{
    __shared__ float Xs[16][65];
    __shared__ float Ws[16][65];
    const int tx = threadIdx.x, ty = threadIdx.y;
    const int tid = ty * 16 + tx;
    const int t0 = blockIdx.x * 64;
    const int b  = blockIdx.y;

    float acc[4][4] = {};
    for (int c0 = 0; c0 < NC; c0 += 16) {
        #pragma unroll
        for (int j = 0; j < 4; j++) {
            int idx = tid + j * 256;
            int tl = idx >> 4, kk = idx & 15;
            int t = t0 + tl;
            float val = 0.f;
            if (t < T2) {
                size_t gi = ((size_t)b * T2 + t) * NC + c0 + kk;
                val = __half2float(xh[gi]) + __half2float(xl[gi]);
            }
            Xs[kk][tl] = val;
        }
        #pragma unroll
        for (int j = 0; j < 4; j++) {
            int idx = tid + j * 256;
            int dl = idx & 63, kk = idx >> 6;
            Ws[kk][dl] = w6[dl * NC + c0 + kk];
        }
        __syncthreads();
        #pragma unroll
        for (int k = 0; k < 16; k++) {
            float a[4], wv[4];
            #pragma unroll
            for (int i = 0; i < 4; i++) a[i] = Xs[k][ty * 4 + i];
            #pragma unroll
            for (int j = 0; j < 4; j++) wv[j] = Ws[k][tx * 4 + j];
            #pragma unroll
            for (int i = 0; i < 4; i++)
                #pragma unroll
                for (int j = 0; j < 4; j++)
                    acc[i][j] = fmaf(a[i], wv[j], acc[i][j]);
        }
        __syncthreads();
    }
    #pragma unroll
    for (int i = 0; i < 4; i++) {
        int t = t0 + ty * 4 + i;
        if (t < T2) {
            #pragma unroll
            for (int j = 0; j < 4; j++) {
                int d = tx * 4 + j;
                z[((size_t)b * T2 + t) * ND + d] = acc[i][j] + b6[d];
            }
        }
    }
}

// ---------------- VQ distance GEMM (fp32) ----------------
__global__ __launch_bounds__(256)
void dist_k(const float* __restrict__ emb)
{
    __shared__ float zs[64][65];
    __shared__ float es[64][65];
    const int tx = threadIdx.x, ty = threadIdx.y;
    const int tid = ty * 16 + tx;
    const int row0 = blockIdx.x * 64;
    const int e0   = blockIdx.y * 64;

    #pragma unroll
    for (int j = 0; j < 16; j++) {
        int idx = tid + j * 256;
        int k = idx & 63, r = idx >> 6;
        zs[r][k] = (row0 + r < NQ) ? g_z[(size_t)(row0 + r) * ND + k] : 0.f;
    }
    #pragma unroll
    for (int j = 0; j < 16; j++) {
        int idx = tid + j * 256;
        int k = idx & 63, e = idx >> 6;
        es[e][k] = emb[(size_t)(e0 + e) * ND + k];
    }
    __syncthreads();

    float acc[4][4] = {};
    #pragma unroll
    for (int k = 0; k < 64; k++) {
        float a[4], b[4];
        #pragma unroll
        for (int i = 0; i < 4; i++) a[i] = zs[ty * 4 + i][k];
        #pragma unroll
        for (int j = 0; j < 4; j++) b[j] = es[tx * 4 + j][k];
        #pragma unroll
        for (int i = 0; i < 4; i++)
            #pragma unroll
            for (int j = 0; j < 4; j++)
                acc[i][j] = fmaf(a[i], b[j], acc[i][j]);
    }

    #pragma unroll
    for (int i = 0; i < 4; i++) {
        int row = row0 + ty * 4 + i;
        if (row < NQ) {
            #pragma unroll
            for (int j = 0; j < 4; j++) {
                int e = e0 + tx * 4 + j;
                g_dist[(size_t)row * NM + e] = g_e2[e] - 2.f * acc[i][j];
            }
        }
    }
}

// ---------------- argmin + quantize + loss + counts ----------------
__global__ __launch_bounds__(256)
void vq_k(const float* __restrict__ emb, float* __restrict__ out_q)
{
    const int warp = threadIdx.x >> 5;
    const int lane = threadIdx.x & 31;
    const int row = blockIdx.x * 8 + warp;
    const float* dr = g_dist + (size_t)row * NM;

    float best = 3.4e38f; int bi = NM;
    #pragma unroll
    for (int i = 0; i < 16; i++) {
        int e = i * 32 + lane;
        float v = dr[e];
        if (v < best) { best = v; bi = e; }
    }
    #pragma unroll
    for (int off = 16; off > 0; off >>= 1) {
        float ob = __shfl_down_sync(0xffffffffu, best, off);
        int   oi = __shfl_down_sync(0xffffffffu, bi,   off);
        if (ob < best || (ob == best && oi < bi)) { best = ob; bi = oi; }
    }
    bi = __shfl_sync(0xffffffffu, bi, 0);

    const float* zr = g_z + (size_t)row * ND;
    const float* er = emb + (size_t)bi * ND;
    float lsum = 0.f;
    #pragma unroll
    for (int d0 = 0; d0 < ND; d0 += 32) {
        int d = d0 + lane;
        float zv = zr[d], qv = er[d];
        out_q[(size_t)row * ND + d] = zv + (qv - zv);
        float df = zv - qv;
        lsum += df * df;
    }
    #pragma unroll
    for (int off = 16; off > 0; off >>= 1)
        lsum += __shfl_down_sync(0xffffffffu, lsum, off);
    if (lane == 0) {
        atomicAdd(&g_loss[0], lsum);
        atomicAdd(&g_counts[bi], 1);
    }
}

__global__ void finalize_k(float* __restrict__ out)
{
    __shared__ float sh[NM];
    int tid = threadIdx.x;
    float p = (float)g_counts[tid] / (float)NQ;
    sh[tid] = -p * logf(p + 1e-10f);
    __syncthreads();
    for (int s = NM / 2; s > 0; s >>= 1) {
        if (tid < s) sh[tid] += sh[tid + s];
        __syncthreads();
    }
    if (tid == 0) {
        out[NQE]     = 0.25f * g_loss[0] / (float)NQE;
        out[NQE + 1] = expf(sh[0]);
    }
}

// ---------------- host-side driver ----------------
static void encoder_run(const float* mels, const float* w1, const float* w2,
                        const float* w3, const float* w4, const float* w5,
                        const float* w6, const float* b6,
                        const float* bng, const float* bnb,
                        const float* bnm, const float* bnv,
                        const float* emb, float* out)
{
    uint32_t *pmels, *pw1;
    __half *pAh, *pAl, *pBh, *pBl, *w2h, *w2l, *w3h, *w3l, *w4h, *w4l, *w5h, *w5l;
    float *zbuf, *bnInv, *bnBeta;
    cudaGetSymbolAddress((void**)&pmels, g_pmels);
    cudaGetSymbolAddress((void**)&pw1, g_pw1);
    cudaGetSymbolAddress((void**)&pAh, g_pA_h);
    cudaGetSymbolAddress((void**)&pAl, g_pA_l);
    cudaGetSymbolAddress((void**)&pBh, g_pB_h);
    cudaGetSymbolAddress((void**)&pBl, g_pB_l);
    cudaGetSymbolAddress((void**)&w2h, g_w2h);  cudaGetSymbolAddress((void**)&w2l, g_w2l);
    cudaGetSymbolAddress((void**)&w3h, g_w3h);  cudaGetSymbolAddress((void**)&w3l, g_w3l);
    cudaGetSymbolAddress((void**)&w4h, g_w4h);  cudaGetSymbolAddress((void**)&w4l, g_w4l);
    cudaGetSymbolAddress((void**)&w5h, g_w5h);  cudaGetSymbolAddress((void**)&w5l, g_w5l);
    cudaGetSymbolAddress((void**)&zbuf, g_z);
    cudaGetSymbolAddress((void**)&bnInv,  g_bnInv);
    cudaGetSymbolAddress((void**)&bnBeta, g_bnBeta);

    cudaFuncSetAttribute(conv1_k,  cudaFuncAttributeMaxDynamicSharedMemorySize, SMEM_BYTES);
    cudaFuncSetAttribute(conv2_k,  cudaFuncAttributeMaxDynamicSharedMemorySize, SMEM_BYTES);
    cudaFuncSetAttribute(conv3_k,  cudaFuncAttributeMaxDynamicSharedMemorySize, SMEM_BYTES);
    cudaFuncSetAttribute(conv45_k, cudaFuncAttributeMaxDynamicSharedMemorySize, SMEM_BYTES);

    zero_k<<<1, 576>>>();
    bnprep_k<<<(5 * NC + 255) / 256, 256>>>(bng, bnb, bnm, bnv);
    e2_k<<<2, 256>>>(emb);
    packw_k<<<(NC * KK1 + 255) / 256, 256>>>(w1, pw1, NC * KK1);
    packwpl_k<<<(NC * KK2 + 255) / 256, 256>>>(w2, w2h, w2l, 3);
    packwpl_k<<<(NC * KK3 + 255) / 256, 256>>>(w3, w3h, w3l, 4);
    packwpl_k<<<(NC * KK2 + 255) / 256, 256>>>(w4, w4h, w4l, 3);
    packwpl_k<<<(NC * KK2 + 255) / 256, 256>>>(w5, w5h, w5l, 3);
    packx_k<<<(NB * CIN0 * T0 + 255) / 256, 256>>>(mels, pmels, NB * CIN0 * T0);

    // conv1: [32,80,1024] -> channel-last planes A [32,1022,768]
    conv1_k<<<dim3((NB * T1 + 127) / 128, NC / 128), 256, SMEM_BYTES>>>(
        pmels, pw1, bnInv + 0 * NC, bnBeta + 0 * NC, pAh, pAl);
    // conv2: A -> B
    conv2_k<<<dim3((NB * T1 + 127) / 128, NC / 128), 256, SMEM_BYTES>>>(
        pAh, pAl, w2h, w2l, bnInv + 1 * NC, bnBeta + 1 * NC, pBh, pBl);
    // conv3 (stride 2): B -> A  [32,511,768]
    conv3_k<<<dim3((NB * T2 + 127) / 128, NC / 128), 256, SMEM_BYTES>>>(
        pBh, pBl, w3h, w3l, bnInv + 2 * NC, bnBeta + 2 * NC, pAh, pAl);
    // conv4: A -> B
    conv45_k<<<dim3((NB * T2 + 127) / 128, NC / 128), 256, SMEM_BYTES>>>(
        pAh, pAl, w4h, w4l, bnInv + 3 * NC, bnBeta + 3 * NC, pBh, pBl);
    // conv5: B -> A
    conv45_k<<<dim3((NB * T2 + 127) / 128, NC / 128), 256, SMEM_BYTES>>>(
        pBh, pBl, w5h, w5l, bnInv + 4 * NC, bnBeta + 4 * NC, pAh, pAl);
    // 1x1 projection -> z
    conv6_k<<<dim3((T2 + 63) / 64, NB), dim3(16, 16)>>>(pAh, pAl, w6, b6, zbuf);
    // VQ
    dist_k<<<dim3((NQ + 63) / 64, NM / 64), dim3(16, 16)>>>(emb);
    vq_k<<<NQ / 8, 256>>>(emb, out);
    finalize_k<<<1, NM>>>(out);
}

extern "C" void kernel_launch(void* const* d_in, const int* in_sizes, int n_in,
                              void* d_out, int out_size)
{
    encoder_run((const float*)d_in[0], (const float*)d_in[1], (const float*)d_in[2],
                (const float*)d_in[3], (const float*)d_in[4], (const float*)d_in[5],
                (const float*)d_in[6], (const float*)d_in[7], (const float*)d_in[8],
                (const float*)d_in[9], (const float*)d_in[10], (const float*)d_in[11],
                (const float*)d_in[12], (float*)d_out);
}

// round 12
// speedup vs baseline: 2.2129x; 1.0613x over previous
#include <cuda_runtime.h>
#include <cuda_fp16.h>
#include <cstdint>
#include <math.h>

// ---------------- problem constants ----------------
constexpr int NB   = 32;
constexpr int NC   = 768;
constexpr int CIN0 = 80;
constexpr int T0   = 1024;
constexpr int T1   = 1022;
constexpr int T2   = 511;
constexpr int ND   = 64;
constexpr int NM   = 512;
constexpr int NQ   = NB * T2;
constexpr int NQE  = NQ * ND;
constexpr float BN_EPS = 1e-5f;
constexpr float WSCALE = 1024.0f;

constexpr int KK1 = CIN0 * 3;     // 240  (conv1, k = ci*KW+kp order)
constexpr int KK2 = NC * 3;       // 2304 (k = kp*CIN+ci order)
constexpr int KK3 = NC * 4;       // 3072

// conv1 (legacy padded layout)
constexpr int LDH       = 40;
constexpr int PLANE1_B  = 128 * LDH * 2;      // 10240
constexpr int STAGE1_B  = 4 * PLANE1_B;       // 40960
constexpr int SMEM1     = 2 * STAGE1_B;       // 81920

// convs 2-5 (swizzled 64B rows, 3 stages)
constexpr int ROWB   = 64;                    // bytes per row (32 halves)
constexpr int PL     = 128 * ROWB;            // 8192 per plane
constexpr int STG    = 4 * PL;                // 32768 (Ah, Al, Bh, Bl)
constexpr int SMEM2  = 3 * STG;               // 98304

// ---------------- scratch ----------------
__device__ uint32_t g_pmels[NB * CIN0 * T0];
__device__ uint32_t g_pw1[NC * KK1];
__device__ __half g_pA_h[NB * T1 * NC];
__device__ __half g_pA_l[NB * T1 * NC];
__device__ __half g_pB_h[NB * T1 * NC];
__device__ __half g_pB_l[NB * T1 * NC];
__device__ __half g_w2h[NC * KK2], g_w2l[NC * KK2];
__device__ __half g_w3h[NC * KK3], g_w3l[NC * KK3];
__device__ __half g_w4h[NC * KK2], g_w4l[NC * KK2];
__device__ __half g_w5h[NC * KK2], g_w5l[NC * KK2];
__device__ float g_z[NQE];
__device__ float g_dist[NQ * NM];
__device__ float g_bnInv[5 * NC];
__device__ float g_bnBeta[5 * NC];
__device__ float g_e2[NM];
__device__ int   g_counts[NM];
__device__ float g_loss[1];

// ---------------- helpers ----------------
__device__ __forceinline__ uint32_t packsplit(float v) {
    __half h = __float2half_rn(v);
    float  r = v - __half2float(h);
    __half l = __float2half_rn(r);
    return (uint32_t)__half_as_ushort(h) | ((uint32_t)__half_as_ushort(l) << 16);
}

__device__ __forceinline__ void mma16816(float* c, const uint32_t* a, const uint32_t* b) {
    asm volatile(
        "mma.sync.aligned.m16n8k16.row.col.f32.f16.f16.f32 "
        "{%0,%1,%2,%3}, {%4,%5,%6,%7}, {%8,%9}, {%0,%1,%2,%3};"
        : "+f"(c[0]), "+f"(c[1]), "+f"(c[2]), "+f"(c[3])
        : "r"(a[0]), "r"(a[1]), "r"(a[2]), "r"(a[3]), "r"(b[0]), "r"(b[1]));
}

__device__ __forceinline__ void cpa16(uint32_t d, const void* s, int sz) {
    asm volatile("cp.async.cg.shared.global [%0], [%1], 16, %2;"
                 :: "r"(d), "l"(s), "r"(sz) : "memory");
}
__device__ __forceinline__ void cp_commit() {
    asm volatile("cp.async.commit_group;" ::: "memory");
}
__device__ __forceinline__ void cp_wait1() {
    asm volatile("cp.async.wait_group 1;" ::: "memory");
}
__device__ __forceinline__ void cp_wait0() {
    asm volatile("cp.async.wait_group 0;" ::: "memory");
}

__device__ __forceinline__ void ldsm_x4(uint32_t* r, uint32_t a) {
    asm volatile("ldmatrix.sync.aligned.m8n8.x4.shared.b16 {%0,%1,%2,%3}, [%4];"
                 : "=r"(r[0]), "=r"(r[1]), "=r"(r[2]), "=r"(r[3]) : "r"(a));
}

// ---------------- tiny prep kernels ----------------
__global__ void zero_k() {
    int i = threadIdx.x;
    if (i < NM) g_counts[i] = 0;
    if (i == NM) g_loss[0] = 0.f;
}

__global__ void bnprep_k(const float* __restrict__ g, const float* __restrict__ b,
                         const float* __restrict__ m, const float* __restrict__ v) {
    int i = blockIdx.x * blockDim.x + threadIdx.x;
    if (i < 5 * NC) {
        float inv = g[i] * rsqrtf(v[i] + BN_EPS);
        g_bnInv[i]  = inv / WSCALE;
        g_bnBeta[i] = b[i] - m[i] * inv;
    }
}

__global__ void packw_k(const float* __restrict__ w, uint32_t* __restrict__ pw, int n) {
    int i = blockIdx.x * blockDim.x + threadIdx.x;
    if (i < n) pw[i] = packsplit(w[i] * WSCALE);
}

__global__ void packx_k(const float* __restrict__ x, uint32_t* __restrict__ px, int n) {
    int i = blockIdx.x * blockDim.x + threadIdx.x;
    if (i < n) px[i] = packsplit(x[i]);
}

__global__ void packwpl_k(const float* __restrict__ w, __half* __restrict__ wh,
                          __half* __restrict__ wl, int KW_) {
    int i = blockIdx.x * blockDim.x + threadIdx.x;
    int KKt = NC * KW_;
    if (i < NC * KKt) {
        int m = i / KKt;
        int k = i - m * KKt;
        int kp = k / NC;
        int ci = k - kp * NC;
        float v = w[(size_t)m * KKt + ci * KW_ + kp] * WSCALE;
        __half h = __float2half_rn(v);
        wh[i] = h;
        wl[i] = __float2half_rn(v - __half2float(h));
    }
}

__global__ void e2_k(const float* __restrict__ emb) {
    int e = blockIdx.x * blockDim.x + threadIdx.x;
    if (e < NM) {
        float s = 0.f;
        #pragma unroll
        for (int d = 0; d < ND; d++) { float t = emb[e * ND + d]; s += t * t; }
        g_e2[e] = s;
    }
}

// ================= conv1 (CIN=80): round-9 style, writes channel-last planes ==========
__global__ __launch_bounds__(256, 2)
void conv1_k(const uint32_t* __restrict__ x, const uint32_t* __restrict__ w,
             const float* __restrict__ inv, const float* __restrict__ bet,
             __half* __restrict__ oh, __half* __restrict__ ol)
{
    constexpr int KW = 3, STRIDE = 1, PAD = 0, CIN = CIN0, TIN = T0, TOUT = T1;
    constexpr int KK = CIN * KW;
    constexpr int NS = (KK + 31) / 32;
    constexpr int NCOLS = NB * TOUT;

    extern __shared__ char smem[];
    const int tid  = threadIdx.x;
    const int lane = tid & 31;
    const int warp = tid >> 5;
    const int gid  = lane >> 2;
    const int tig  = lane & 3;
    const int mw   = warp >> 2;
    const int nw   = warp & 3;
    const int m0 = blockIdx.y * 128;
    const int n0 = blockIdx.x * 128;

    const int arow = tid >> 1;
    const int ak0  = (tid & 1) * 16;
    const int bn   = tid & 127;
    const int bk0  = (tid >> 7) * 16;
    const int ncolB = n0 + bn;
    const bool cv   = ncolB < NCOLS;
    const int nbB = cv ? (ncolB / TOUT) : 0;
    const int tB  = cv ? (ncolB - nbB * TOUT) : 0;
    const uint32_t* xrow = x + (size_t)nbB * CIN * TIN;
    const uint32_t* wrow = w + (size_t)(m0 + arow) * KK;

    uint32_t ar[16], br[16];
    float acc[4][4][4];
    #pragma unroll
    for (int a = 0; a < 4; a++)
        #pragma unroll
        for (int b = 0; b < 4; b++)
            #pragma unroll
            for (int c = 0; c < 4; c++) acc[a][b][c] = 0.f;

    auto LOADS = [&](int kt) {
        #pragma unroll
        for (int j = 0; j < 4; j++) {
            int kk = kt + ak0 + j * 4;
            #pragma unroll
            for (int q = 0; q < 4; q++)
                ar[j*4+q] = (kk + q < KK) ? wrow[kk + q] : 0u;
        }
        #pragma unroll
        for (int i = 0; i < 16; i++) {
            int kk = kt + bk0 + i;
            uint32_t v = 0u;
            if (cv && kk < KK) {
                int ci = kk / KW, kp = kk - ci * KW;
                int tin = tB * STRIDE + kp - PAD;
                if (tin >= 0 && tin < TIN) v = xrow[(size_t)ci * TIN + tin];
            }
            br[i] = v;
        }
    };

    auto STORES = [&](int s) {
        __half* Ah = (__half*)(smem + s * STAGE1_B);
        __half* Al = Ah + 128 * LDH;
        __half* Bh = Al + 128 * LDH;
        __half* Bl = Bh + 128 * LDH;
        #pragma unroll
        for (int i = 0; i < 8; i++) {
            uint32_t hiA = __byte_perm(ar[2*i], ar[2*i+1], 0x5410);
            uint32_t loA = __byte_perm(ar[2*i], ar[2*i+1], 0x7632);
            *(uint32_t*)&Ah[arow * LDH + ak0 + 2*i] = hiA;
            *(uint32_t*)&Al[arow * LDH + ak0 + 2*i] = loA;
            uint32_t hiB = __byte_perm(br[2*i], br[2*i+1], 0x5410);
            uint32_t loB = __byte_perm(br[2*i], br[2*i+1], 0x7632);
            *(uint32_t*)&Bh[bn * LDH + bk0 + 2*i] = hiB;
            *(uint32_t*)&Bl[bn * LDH + bk0 + 2*i] = loB;
        }
    };

    auto COMPUTE = [&](int s) {
        const __half* Ah = (const __half*)(smem + s * STAGE1_B);
        const __half* Al = Ah + 128 * LDH;
        const __half* Bh = Al + 128 * LDH;
        const __half* Bl = Bh + 128 * LDH;
        #pragma unroll
        for (int kh = 0; kh < 2; kh++) {
            const int k16 = kh * 16;
            uint32_t aH[4][4], aL[4][4];
            #pragma unroll
            for (int mi = 0; mi < 4; mi++) {
                int r = mw * 64 + mi * 16 + gid;
                aH[mi][0] = *(const uint32_t*)&Ah[ r      * LDH + k16 + 2*tig    ];
                aH[mi][1] = *(const uint32_t*)&Ah[(r + 8) * LDH + k16 + 2*tig    ];
                aH[mi][2] = *(const uint32_t*)&Ah[ r      * LDH + k16 + 2*tig + 8];
                aH[mi][3] = *(const uint32_t*)&Ah[(r + 8) * LDH + k16 + 2*tig + 8];
                aL[mi][0] = *(const uint32_t*)&Al[ r      * LDH + k16 + 2*tig    ];
                aL[mi][1] = *(const uint32_t*)&Al[(r + 8) * LDH + k16 + 2*tig    ];
                aL[mi][2] = *(const uint32_t*)&Al[ r      * LDH + k16 + 2*tig + 8];
                aL[mi][3] = *(const uint32_t*)&Al[(r + 8) * LDH + k16 + 2*tig + 8];
            }
            #pragma unroll
            for (int ni = 0; ni < 4; ni++) {
                int n = nw * 32 + ni * 8 + gid;
                uint32_t bH[2], bL[2];
                bH[0] = *(const uint32_t*)&Bh[n * LDH + k16 + 2*tig    ];
                bH[1] = *(const uint32_t*)&Bh[n * LDH + k16 + 2*tig + 8];
                bL[0] = *(const uint32_t*)&Bl[n * LDH + k16 + 2*tig    ];
                bL[1] = *(const uint32_t*)&Bl[n * LDH + k16 + 2*tig + 8];
                #pragma unroll
                for (int mi = 0; mi < 4; mi++) {
                    mma16816(acc[mi][ni], aH[mi], bH);
                    mma16816(acc[mi][ni], aH[mi], bL);
                    mma16816(acc[mi][ni], aL[mi], bH);
                }
            }
        }
    };

    LOADS(0);
    STORES(0);
    __syncthreads();
    for (int s = 0; s < NS; s++) {
        if (s + 1 < NS) {
            LOADS((s + 1) * 32);
            STORES((s + 1) & 1);
        }
        COMPUTE(s & 1);
        __syncthreads();
    }

    #pragma unroll
    for (int mi = 0; mi < 4; mi++) {
        int r1 = m0 + mw * 64 + mi * 16 + gid;
        int r2 = r1 + 8;
        float iv1 = inv[r1], bb1 = bet[r1];
        float iv2 = inv[r2], bb2 = bet[r2];
        #pragma unroll
        for (int ni = 0; ni < 4; ni++) {
            int nc = n0 + nw * 32 + ni * 8 + 2 * tig;
            #pragma unroll
            for (int q = 0; q < 2; q++) {
                int ncol = nc + q;
                if (ncol < NCOLS) {
                    float v1 = acc[mi][ni][q]     * iv1 + bb1;
                    float v2 = acc[mi][ni][2 + q] * iv2 + bb2;
                    v1 = v1 > 0.f ? v1 : 0.f;
                    v2 = v2 > 0.f ? v2 : 0.f;
                    size_t base = (size_t)ncol * NC;
                    __half h1 = __float2half_rn(v1);
                    __half h2 = __float2half_rn(v2);
                    oh[base + r1] = h1;
                    ol[base + r1] = __float2half_rn(v1 - __half2float(h1));
                    oh[base + r2] = h2;
                    ol[base + r2] = __float2half_rn(v2 - __half2float(h2));
                }
            }
        }
    }
}

// ===== convs 2-5: swizzled 64B rows, 3-stage cp.async pipeline, 1 sync/stage =====
template<int KW, int STRIDE, int PAD, int TIN, int TOUT>
__device__ __forceinline__
void conv_cl_body(const __half* __restrict__ xh, const __half* __restrict__ xl,
                  const __half* __restrict__ wh, const __half* __restrict__ wl,
                  const float* __restrict__ inv, const float* __restrict__ bet,
                  __half* __restrict__ oh, __half* __restrict__ ol)
{
    constexpr int CIN = NC;
    constexpr int KK  = CIN * KW;
    constexpr int NS  = KK / 32;
    constexpr int NCOLS = NB * TOUT;

    extern __shared__ char smem[];
    const uint32_t sbase = (uint32_t)__cvta_generic_to_shared(smem);

    const int tid  = threadIdx.x;
    const int lane = tid & 31;
    const int warp = tid >> 5;
    const int gid  = lane >> 2;
    const int tig  = lane & 3;
    const int mw   = warp >> 2;
    const int nw   = warp & 3;
    const int m0 = blockIdx.y * 128;
    const int n0 = blockIdx.x * 128;

    // cp.async task: tid<128 -> A row; tid>=128 -> B row
    const int rrow = tid & 127;
    const bool isA = tid < 128;
    const int ncolB = n0 + rrow;
    const bool cvB  = ncolB < NCOLS;
    const int nbB = cvB ? (ncolB / TOUT) : 0;
    const int tB  = cvB ? (ncolB - nbB * TOUT) : 0;
    const __half* wrh = wh + (size_t)(m0 + rrow) * KK;
    const __half* wrl = wl + (size_t)(m0 + rrow) * KK;
    const int swR = (rrow >> 1) & 3;
    const uint32_t dstbase = (isA ? 0u : 2u * PL) + (uint32_t)rrow * ROWB;

    // precomputed ldsm offsets (stage-invariant)
    uint32_t offA[2][4], offB[2][2];
    {
        const int cbA = lane >> 4;          // chunk bit for A
        #pragma unroll
        for (int mi = 0; mi < 4; mi++) {
            int r = mw * 64 + mi * 16 + (lane & 15);
            int sw = (r >> 1) & 3;
            #pragma unroll
            for (int kh = 0; kh < 2; kh++)
                offA[kh][mi] = (uint32_t)(r * ROWB + ((((kh * 2 + cbA) ^ sw) & 3) << 4));
        }
        const int cbB = (lane >> 3) & 1;    // chunk bit for B
        const int gB  = (lane >> 4) & 1;    // ni-high bit within pair
        #pragma unroll
        for (int q = 0; q < 2; q++) {
            int r = nw * 32 + (q * 2 + gB) * 8 + (lane & 7);
            int sw = (r >> 1) & 3;
            #pragma unroll
            for (int kh = 0; kh < 2; kh++)
                offB[kh][q] = (uint32_t)(r * ROWB + ((((kh * 2 + cbB) ^ sw) & 3) << 4));
        }
    }

    float acc[4][4][4];
    #pragma unroll
    for (int a = 0; a < 4; a++)
        #pragma unroll
        for (int b = 0; b < 4; b++)
            #pragma unroll
            for (int c = 0; c < 4; c++) acc[a][b][c] = 0.f;

    auto ISSUE = [&](int s) {
        const uint32_t stb = sbase + (uint32_t)(s % 3) * STG + dstbase;
        const int kt = s * 32;
        if (isA) {
            const __half* sh = wrh + kt;
            const __half* sl = wrl + kt;
            #pragma unroll
            for (int c = 0; c < 4; c++) {
                uint32_t d = stb + (uint32_t)(((c ^ swR) & 3) << 4);
                cpa16(d,      sh + c * 8, 16);
                cpa16(d + PL, sl + c * 8, 16);
            }
        } else {
            int kp  = kt / CIN;
            int ci0 = kt - kp * CIN;
            int tin = tB * STRIDE + kp - PAD;
            bool ok = cvB && tin >= 0 && tin < TIN;
            int tin_c = ok ? tin : 0;
            const __half* sh = xh + ((size_t)nbB * TIN + tin_c) * CIN + ci0;
            const __half* sl = xl + ((size_t)nbB * TIN + tin_c) * CIN + ci0;
            int sz = ok ? 16 : 0;
            #pragma unroll
            for (int c = 0; c < 4; c++) {
                uint32_t d = stb + (uint32_t)(((c ^ swR) & 3) << 4);
                cpa16(d,      sh + c * 8, sz);
                cpa16(d + PL, sl + c * 8, sz);
            }
        }
        cp_commit();
    };

    auto COMPUTE = [&](int st) {
        const uint32_t pA = sbase + (uint32_t)st * STG;
        const uint32_t pB = pA + 2u * PL;
        #pragma unroll
        for (int kh = 0; kh < 2; kh++) {
            uint32_t bH[4][2], bL[4][2];
            {
                uint32_t t[4];
                ldsm_x4(t, pB + offB[kh][0]);
                bH[0][0] = t[0]; bH[0][1] = t[1]; bH[1][0] = t[2]; bH[1][1] = t[3];
                ldsm_x4(t, pB + offB[kh][1]);
                bH[2][0] = t[0]; bH[2][1] = t[1]; bH[3][0] = t[2]; bH[3][1] = t[3];
                ldsm_x4(t, pB + PL + offB[kh][0]);
                bL[0][0] = t[0]; bL[0][1] = t[1]; bL[1][0] = t[2]; bL[1][1] = t[3];
                ldsm_x4(t, pB + PL + offB[kh][1]);
                bL[2][0] = t[0]; bL[2][1] = t[1]; bL[3][0] = t[2]; bL[3][1] = t[3];
            }
            #pragma unroll
            for (int mi = 0; mi < 4; mi++) {
                uint32_t aH[4], aL[4];
                ldsm_x4(aH, pA + offA[kh][mi]);
                ldsm_x4(aL, pA + PL + offA[kh][mi]);
                #pragma unroll
                for (int ni = 0; ni < 4; ni++) {
                    mma16816(acc[mi][ni], aH, bH[ni]);
                    mma16816(acc[mi][ni], aH, bL[ni]);
                    mma16816(acc[mi][ni], aL, bH[ni]);
                }
            }
        }
    };

    ISSUE(0);
    ISSUE(1);
    for (int s = 0; s < NS; s++) {
        if (s + 1 < NS) cp_wait1(); else cp_wait0();
        __syncthreads();
        if (s + 2 < NS) ISSUE(s + 2);
        COMPUTE(s % 3);
    }

    // epilogue: BN+ReLU -> channel-last hi/lo planes
    #pragma unroll
    for (int mi = 0; mi < 4; mi++) {
        int r1 = m0 + mw * 64 + mi * 16 + gid;
        int r2 = r1 + 8;
        float iv1 = inv[r1], bb1 = bet[r1];
        float iv2 = inv[r2], bb2 = bet[r2];
        #pragma unroll
        for (int ni = 0; ni < 4; ni++) {
            int nc = n0 + nw * 32 + ni * 8 + 2 * tig;
            #pragma unroll
            for (int q = 0; q < 2; q++) {
                int ncol = nc + q;
                if (ncol < NCOLS) {
                    float v1 = acc[mi][ni][q]     * iv1 + bb1;
                    float v2 = acc[mi][ni][2 + q] * iv2 + bb2;
                    v1 = v1 > 0.f ? v1 : 0.f;
                    v2 = v2 > 0.f ? v2 : 0.f;
                    size_t base = (size_t)ncol * NC;
                    __half h1 = __float2half_rn(v1);
                    __half h2 = __float2half_rn(v2);
                    oh[base + r1] = h1;
                    ol[base + r1] = __float2half_rn(v1 - __half2float(h1));
                    oh[base + r2] = h2;
                    ol[base + r2] = __float2half_rn(v2 - __half2float(h2));
                }
            }
        }
    }
}

__global__ __launch_bounds__(256, 2)
void conv2_k(const __half* xh, const __half* xl, const __half* wh, const __half* wl,
             const float* inv, const float* bet, __half* oh, __half* ol) {
    conv_cl_body<3, 1, 1, T1, T1>(xh, xl, wh, wl, inv, bet, oh, ol);
}
__global__ __launch_bounds__(256, 2)
void conv3_k(const __half* xh, const __half* xl, const __half* wh, const __half* wl,
             const float* inv, const float* bet, __half* oh, __half* ol) {
    conv_cl_body<4, 2, 1, T1, T2>(xh, xl, wh, wl, inv, bet, oh, ol);
}
__global__ __launch_bounds__(256, 2)
void conv45_k(const __half* xh, const __half* xl, const __half* wh, const __half* wl,
              const float* inv, const float* bet, __half* oh, __half* ol) {
    conv_cl_body<3, 1, 1, T2, T2>(xh, xl, wh, wl, inv, bet, oh, ol);
}

// ---------------- 1x1 projection + bias -> z [B, T', D] (channel-last input) ----------
__global__ __launch_bounds__(256)
void conv6_k(const __half* __restrict__ xh, const __half* __restrict__ xl,
             const float* __restrict__ w6, const float* __restrict__ b6,
             float* __restrict__ z)
{
    __shared__ float Xs[16][65];
    __shared__ float Ws[16][65];
    const int tx = threadIdx.x, ty = threadIdx.y;
    const int tid = ty * 16 + tx;
    const int t0 = blockIdx.x * 64;
    const int b  = blockIdx.y;

    float acc[4][4] = {};
    for (int c0 = 0; c0 < NC; c0 += 16) {
        #pragma unroll
        for (int j = 0; j < 4; j++) {
            int idx = tid + j * 256;
            int tl = idx >> 4, kk = idx & 15;
            int t = t0 + tl;
            float val = 0.f;
            if (t < T2) {
                size_t gi = ((size_t)b * T2 + t) * NC + c0 + kk;
                val = __half2float(xh[gi]) + __half2float(xl[gi]);
            }
            Xs[kk][tl] = val;
        }
        #pragma unroll
        for (int j = 0; j < 4; j++) {
            int idx = tid + j * 256;
            int dl = idx & 63, kk = idx >> 6;
            Ws[kk][dl] = w6[dl * NC + c0 + kk];
        }
        __syncthreads();
        #pragma unroll
        for (int k = 0; k < 16; k++) {
            float a[4], wv[4];
            #pragma unroll
            for (int i = 0; i < 4; i++) a[i] = Xs[k][ty * 4 + i];
            #pragma unroll
            for (int j = 0; j < 4; j++) wv[j] = Ws[k][tx * 4 + j];
            #pragma unroll
            for (int i = 0; i < 4; i++)
                #pragma unroll
                for (int j = 0; j < 4; j++)
                    acc[i][j] = fmaf(a[i], wv[j], acc[i][j]);
        }
        __syncthreads();
    }
    #pragma unroll
    for (int i = 0; i < 4; i++) {
        int t = t0 + ty * 4 + i;
        if (t < T2) {
            #pragma unroll
            for (int j = 0; j < 4; j++) {
                int d = tx * 4 + j;
                z[((size_t)b * T2 + t) * ND + d] = acc[i][j] + b6[d];
            }
        }
    }
}

// ---------------- VQ distance GEMM (fp32) ----------------
__global__ __launch_bounds__(256)
void dist_k(const float* __restrict__ emb)
{
    __shared__ float zs[64][65];
    __shared__ float es[64][65];
    const int tx = threadIdx.x, ty = threadIdx.y;
    const int tid = ty * 16 + tx;
    const int row0 = blockIdx.x * 64;
    const int e0   = blockIdx.y * 64;

    #pragma unroll
    for (int j = 0; j < 16; j++) {
        int idx = tid + j * 256;
        int k = idx & 63, r = idx >> 6;
        zs[r][k] = (row0 + r < NQ) ? g_z[(size_t)(row0 + r) * ND + k] : 0.f;
    }
    #pragma unroll
    for (int j = 0; j < 16; j++) {
        int idx = tid + j * 256;
        int k = idx & 63, e = idx >> 6;
        es[e][k] = emb[(size_t)(e0 + e) * ND + k];
    }
    __syncthreads();

    float acc[4][4] = {};
    #pragma unroll
    for (int k = 0; k < 64; k++) {
        float a[4], b[4];
        #pragma unroll
        for (int i = 0; i < 4; i++) a[i] = zs[ty * 4 + i][k];
        #pragma unroll
        for (int j = 0; j < 4; j++) b[j] = es[tx * 4 + j][k];
        #pragma unroll
        for (int i = 0; i < 4; i++)
            #pragma unroll
            for (int j = 0; j < 4; j++)
                acc[i][j] = fmaf(a[i], b[j], acc[i][j]);
    }

    #pragma unroll
    for (int i = 0; i < 4; i++) {
        int row = row0 + ty * 4 + i;
        if (row < NQ) {
            #pragma unroll
            for (int j = 0; j < 4; j++) {
                int e = e0 + tx * 4 + j;
                g_dist[(size_t)row * NM + e] = g_e2[e] - 2.f * acc[i][j];
            }
        }
    }
}

// ---------------- argmin + quantize + loss + counts ----------------
__global__ __launch_bounds__(256)
void vq_k(const float* __restrict__ emb, float* __restrict__ out_q)
{
    const int warp = threadIdx.x >> 5;
    const int lane = threadIdx.x & 31;
    const int row = blockIdx.x * 8 + warp;
    const float* dr = g_dist + (size_t)row * NM;

    float best = 3.4e38f; int bi = NM;
    #pragma unroll
    for (int i = 0; i < 16; i++) {
        int e = i * 32 + lane;
        float v = dr[e];
        if (v < best) { best = v; bi = e; }
    }
    #pragma unroll
    for (int off = 16; off > 0; off >>= 1) {
        float ob = __shfl_down_sync(0xffffffffu, best, off);
        int   oi = __shfl_down_sync(0xffffffffu, bi,   off);
        if (ob < best || (ob == best && oi < bi)) { best = ob; bi = oi; }
    }
    bi = __shfl_sync(0xffffffffu, bi, 0);

    const float* zr = g_z + (size_t)row * ND;
    const float* er = emb + (size_t)bi * ND;
    float lsum = 0.f;
    #pragma unroll
    for (int d0 = 0; d0 < ND; d0 += 32) {
        int d = d0 + lane;
        float zv = zr[d], qv = er[d];
        out_q[(size_t)row * ND + d] = zv + (qv - zv);
        float df = zv - qv;
        lsum += df * df;
    }
    #pragma unroll
    for (int off = 16; off > 0; off >>= 1)
        lsum += __shfl_down_sync(0xffffffffu, lsum, off);
    if (lane == 0) {
        atomicAdd(&g_loss[0], lsum);
        atomicAdd(&g_counts[bi], 1);
    }
}

__global__ void finalize_k(float* __restrict__ out)
{
    __shared__ float sh[NM];
    int tid = threadIdx.x;
    float p = (float)g_counts[tid] / (float)NQ;
    sh[tid] = -p * logf(p + 1e-10f);
    __syncthreads();
    for (int s = NM / 2; s > 0; s >>= 1) {
        if (tid < s) sh[tid] += sh[tid + s];
        __syncthreads();
    }
    if (tid == 0) {
        out[NQE]     = 0.25f * g_loss[0] / (float)NQE;
        out[NQE + 1] = expf(sh[0]);
    }
}

// ---------------- host-side driver ----------------
static void encoder_run(const float* mels, const float* w1, const float* w2,
                        const float* w3, const float* w4, const float* w5,
                        const float* w6, const float* b6,
                        const float* bng, const float* bnb,
                        const float* bnm, const float* bnv,
                        const float* emb, float* out)
{
    uint32_t *pmels, *pw1;
    __half *pAh, *pAl, *pBh, *pBl, *w2h, *w2l, *w3h, *w3l, *w4h, *w4l, *w5h, *w5l;
    float *zbuf, *bnInv, *bnBeta;
    cudaGetSymbolAddress((void**)&pmels, g_pmels);
    cudaGetSymbolAddress((void**)&pw1, g_pw1);
    cudaGetSymbolAddress((void**)&pAh, g_pA_h);
    cudaGetSymbolAddress((void**)&pAl, g_pA_l);
    cudaGetSymbolAddress((void**)&pBh, g_pB_h);
    cudaGetSymbolAddress((void**)&pBl, g_pB_l);
    cudaGetSymbolAddress((void**)&w2h, g_w2h);  cudaGetSymbolAddress((void**)&w2l, g_w2l);
    cudaGetSymbolAddress((void**)&w3h, g_w3h);  cudaGetSymbolAddress((void**)&w3l, g_w3l);
    cudaGetSymbolAddress((void**)&w4h, g_w4h);  cudaGetSymbolAddress((void**)&w4l, g_w4l);
    cudaGetSymbolAddress((void**)&w5h, g_w5h);  cudaGetSymbolAddress((void**)&w5l, g_w5l);
    cudaGetSymbolAddress((void**)&zbuf, g_z);
    cudaGetSymbolAddress((void**)&bnInv,  g_bnInv);
    cudaGetSymbolAddress((void**)&bnBeta, g_bnBeta);

    cudaFuncSetAttribute(conv1_k,  cudaFuncAttributeMaxDynamicSharedMemorySize, SMEM1);
    cudaFuncSetAttribute(conv2_k,  cudaFuncAttributeMaxDynamicSharedMemorySize, SMEM2);
    cudaFuncSetAttribute(conv3_k,  cudaFuncAttributeMaxDynamicSharedMemorySize, SMEM2);
    cudaFuncSetAttribute(conv45_k, cudaFuncAttributeMaxDynamicSharedMemorySize, SMEM2);

    zero_k<<<1, 576>>>();
    bnprep_k<<<(5 * NC + 255) / 256, 256>>>(bng, bnb, bnm, bnv);
    e2_k<<<2, 256>>>(emb);
    packw_k<<<(NC * KK1 + 255) / 256, 256>>>(w1, pw1, NC * KK1);
    packwpl_k<<<(NC * KK2 + 255) / 256, 256>>>(w2, w2h, w2l, 3);
    packwpl_k<<<(NC * KK3 + 255) / 256, 256>>>(w3, w3h, w3l, 4);
    packwpl_k<<<(NC * KK2 + 255) / 256, 256>>>(w4, w4h, w4l, 3);
    packwpl_k<<<(NC * KK2 + 255) / 256, 256>>>(w5, w5h, w5l, 3);
    packx_k<<<(NB * CIN0 * T0 + 255) / 256, 256>>>(mels, pmels, NB * CIN0 * T0);

    conv1_k<<<dim3((NB * T1 + 127) / 128, NC / 128), 256, SMEM1>>>(
        pmels, pw1, bnInv + 0 * NC, bnBeta + 0 * NC, pAh, pAl);
    conv2_k<<<dim3((NB * T1 + 127) / 128, NC / 128), 256, SMEM2>>>(
        pAh, pAl, w2h, w2l, bnInv + 1 * NC, bnBeta + 1 * NC, pBh, pBl);
    conv3_k<<<dim3((NB * T2 + 127) / 128, NC / 128), 256, SMEM2>>>(
        pBh, pBl, w3h, w3l, bnInv + 2 * NC, bnBeta + 2 * NC, pAh, pAl);
    conv45_k<<<dim3((NB * T2 + 127) / 128, NC / 128), 256, SMEM2>>>(
        pAh, pAl, w4h, w4l, bnInv + 3 * NC, bnBeta + 3 * NC, pBh, pBl);
    conv45_k<<<dim3((NB * T2 + 127) / 128, NC / 128), 256, SMEM2>>>(
        pBh, pBl, w5h, w5l, bnInv + 4 * NC, bnBeta + 4 * NC, pAh, pAl);
    conv6_k<<<dim3((T2 + 63) / 64, NB), dim3(16, 16)>>>(pAh, pAl, w6, b6, zbuf);
    dist_k<<<dim3((NQ + 63) / 64, NM / 64), dim3(16, 16)>>>(emb);
    vq_k<<<NQ / 8, 256>>>(emb, out);
    finalize_k<<<1, NM>>>(out);
}

extern "C" void kernel_launch(void* const* d_in, const int* in_sizes, int n_in,
                              void* d_out, int out_size)
{
    encoder_run((const float*)d_in[0], (const float*)d_in[1], (const float*)d_in[2],
                (const float*)d_in[3], (const float*)d_in[4], (const float*)d_in[5],
                (const float*)d_in[6], (const float*)d_in[7], (const float*)d_in[8],
                (const float*)d_in[9], (const float*)d_in[10], (const float*)d_in[11],
                (const float*)d_in[12], (float*)d_out);
}

// round 14
// speedup vs baseline: 2.2535x; 1.0183x over previous
#include <cuda_runtime.h>
#include <cuda_fp16.h>
#include <cstdint>
#include <math.h>

// ---------------- problem constants ----------------
constexpr int NB   = 32;
constexpr int NC   = 768;
constexpr int CIN0 = 80;
constexpr int CIN1P = 96;          // conv1 padded channel count (96*3/32 = 9 stages)
constexpr int T0   = 1024;
constexpr int T1   = 1022;
constexpr int T2   = 511;
constexpr int ND   = 64;
constexpr int NM   = 512;
constexpr int NQ   = NB * T2;
constexpr int NQE  = NQ * ND;
constexpr float BN_EPS = 1e-5f;
constexpr float WSCALE = 1024.0f;

constexpr int KK1P = CIN1P * 3;    // 288
constexpr int KK2  = NC * 3;       // 2304
constexpr int KK3  = NC * 4;       // 3072

// swizzled 64B rows, 3 stages
constexpr int ROWB   = 64;
constexpr int PL     = 128 * ROWB;            // 8192 per plane
constexpr int STG    = 4 * PL;                // 32768 (Ah, Al, Bh, Bl)
constexpr int SMEM2  = 3 * STG;               // 98304

// ---------------- scratch ----------------
__device__ __align__(16) __half g_m_h[NB * T0 * CIN1P];   // padded mels planes [b][t][96]
__device__ __align__(16) __half g_m_l[NB * T0 * CIN1P];
__device__ __align__(16) __half g_w1h[NC * KK1P], g_w1l[NC * KK1P];
__device__ __align__(16) __half g_pA_h[NB * T1 * NC];
__device__ __align__(16) __half g_pA_l[NB * T1 * NC];
__device__ __align__(16) __half g_pB_h[NB * T1 * NC];
__device__ __align__(16) __half g_pB_l[NB * T1 * NC];
__device__ __align__(16) __half g_w2h[NC * KK2], g_w2l[NC * KK2];
__device__ __align__(16) __half g_w3h[NC * KK3], g_w3l[NC * KK3];
__device__ __align__(16) __half g_w4h[NC * KK2], g_w4l[NC * KK2];
__device__ __align__(16) __half g_w5h[NC * KK2], g_w5l[NC * KK2];
__device__ float g_z[NQE];
__device__ float g_dist[NQ * NM];
__device__ float g_bnInv[5 * NC];
__device__ float g_bnBeta[5 * NC];
__device__ float g_e2[NM];
__device__ int   g_counts[NM];
__device__ float g_loss[1];

// ---------------- helpers ----------------
__device__ __forceinline__ void splitstore(float v, __half* ph, __half* pl) {
    __half h = __float2half_rn(v);
    *ph = h;
    *pl = __float2half_rn(v - __half2float(h));
}

__device__ __forceinline__ void mma16816(float* c, const uint32_t* a, const uint32_t* b) {
    asm volatile(
        "mma.sync.aligned.m16n8k16.row.col.f32.f16.f16.f32 "
        "{%0,%1,%2,%3}, {%4,%5,%6,%7}, {%8,%9}, {%0,%1,%2,%3};"
        : "+f"(c[0]), "+f"(c[1]), "+f"(c[2]), "+f"(c[3])
        : "r"(a[0]), "r"(a[1]), "r"(a[2]), "r"(a[3]), "r"(b[0]), "r"(b[1]));
}

__device__ __forceinline__ void cpa16(uint32_t d, const void* s, int sz) {
    asm volatile("cp.async.cg.shared.global [%0], [%1], 16, %2;"
                 :: "r"(d), "l"(s), "r"(sz) : "memory");
}
__device__ __forceinline__ void cp_commit() {
    asm volatile("cp.async.commit_group;" ::: "memory");
}
__device__ __forceinline__ void cp_wait1() {
    asm volatile("cp.async.wait_group 1;" ::: "memory");
}
__device__ __forceinline__ void cp_wait0() {
    asm volatile("cp.async.wait_group 0;" ::: "memory");
}

__device__ __forceinline__ void ldsm_x4(uint32_t* r, uint32_t a) {
    asm volatile("ldmatrix.sync.aligned.m8n8.x4.shared.b16 {%0,%1,%2,%3}, [%4];"
                 : "=r"(r[0]), "=r"(r[1]), "=r"(r[2]), "=r"(r[3]) : "r"(a));
}

// ---------------- prep kernels (2 launches total) ----------------
__global__ void prep_k(const float* __restrict__ g, const float* __restrict__ b,
                       const float* __restrict__ m, const float* __restrict__ v,
                       const float* __restrict__ emb) {
    int i = blockIdx.x * blockDim.x + threadIdx.x;
    if (i < 5 * NC) {
        float inv = g[i] * rsqrtf(v[i] + BN_EPS);
        g_bnInv[i]  = inv / WSCALE;
        g_bnBeta[i] = b[i] - m[i] * inv;
    }
    if (i < NM) {
        g_counts[i] = 0;
        float s = 0.f;
        #pragma unroll
        for (int d = 0; d < ND; d++) { float t = emb[i * ND + d]; s += t * t; }
        g_e2[i] = s;
    }
    if (i == NM) g_loss[0] = 0.f;
}

__global__ void packall_k(const float* __restrict__ w1, const float* __restrict__ w2,
                          const float* __restrict__ w3, const float* __restrict__ w4,
                          const float* __restrict__ w5, const float* __restrict__ mels) {
    int i = blockIdx.x * blockDim.x + threadIdx.x;
    // w1: reorder to kp-major, pad CIN 80->96
    if (i < NC * KK1P) {
        int mm = i / KK1P, k = i - mm * KK1P;
        int kp = k / CIN1P, ci = k - kp * CIN1P;
        float v = (ci < CIN0) ? w1[((size_t)mm * CIN0 + ci) * 3 + kp] * WSCALE : 0.f;
        splitstore(v, &g_w1h[i], &g_w1l[i]);
        return;
    }
    i -= NC * KK1P;
    if (i < NC * KK2) {
        int mm = i / KK2, k = i - mm * KK2;
        int kp = k / NC, ci = k - kp * NC;
        float v = w2[((size_t)mm * NC + ci) * 3 + kp] * WSCALE;
        splitstore(v, &g_w2h[i], &g_w2l[i]);
        return;
    }
    i -= NC * KK2;
    if (i < NC * KK3) {
        int mm = i / KK3, k = i - mm * KK3;
        int kp = k / NC, ci = k - kp * NC;
        float v = w3[((size_t)mm * NC + ci) * 4 + kp] * WSCALE;
        splitstore(v, &g_w3h[i], &g_w3l[i]);
        return;
    }
    i -= NC * KK3;
    if (i < NC * KK2) {
        int mm = i / KK2, k = i - mm * KK2;
        int kp = k / NC, ci = k - kp * NC;
        float v = w4[((size_t)mm * NC + ci) * 3 + kp] * WSCALE;
        splitstore(v, &g_w4h[i], &g_w4l[i]);
        return;
    }
    i -= NC * KK2;
    if (i < NC * KK2) {
        int mm = i / KK2, k = i - mm * KK2;
        int kp = k / NC, ci = k - kp * NC;
        float v = w5[((size_t)mm * NC + ci) * 3 + kp] * WSCALE;
        splitstore(v, &g_w5h[i], &g_w5l[i]);
        return;
    }
    i -= NC * KK2;
    if (i < NB * T0 * CIN1P) {
        int bb = i / (T0 * CIN1P), r = i - bb * T0 * CIN1P;
        int t = r / CIN1P, ci = r - t * CIN1P;
        float v = (ci < CIN0) ? mels[((size_t)bb * CIN0 + ci) * T0 + t] : 0.f;
        splitstore(v, &g_m_h[i], &g_m_l[i]);
    }
}
constexpr int PACKALL_N = NC * KK1P + 3 * (NC * KK2) + NC * KK3 + NB * T0 * CIN1P;

// ===== unified conv: channel-last planes, swizzled rows, 3-stage cp.async pipeline =====
template<int CIN, int KW, int STRIDE, int PAD, int TIN, int TOUT>
__device__ __forceinline__
void conv_cl_body(const __half* __restrict__ xh, const __half* __restrict__ xl,
                  const __half* __restrict__ wh, const __half* __restrict__ wl,
                  const float* __restrict__ inv, const float* __restrict__ bet,
                  __half* __restrict__ oh, __half* __restrict__ ol)
{
    constexpr int KK  = CIN * KW;
    constexpr int NS  = KK / 32;
    constexpr int NCOLS = NB * TOUT;

    extern __shared__ char smem[];
    const uint32_t sbase = (uint32_t)__cvta_generic_to_shared(smem);

    const int tid  = threadIdx.x;
    const int lane = tid & 31;
    const int warp = tid >> 5;
    const int gid  = lane >> 2;
    const int tig  = lane & 3;
    const int mw   = warp >> 2;
    const int nw   = warp & 3;
    const int m0 = blockIdx.y * 128;
    const int n0 = blockIdx.x * 128;

    // cp.async task: tid<128 -> A row; tid>=128 -> B row
    const int rrow = tid & 127;
    const bool isA = tid < 128;
    const int ncolB = n0 + rrow;
    const bool cvB  = ncolB < NCOLS;
    const int nbB = cvB ? (ncolB / TOUT) : 0;
    const int tB  = cvB ? (ncolB - nbB * TOUT) : 0;
    const __half* wrh = wh + (size_t)(m0 + rrow) * KK;
    const __half* wrl = wl + (size_t)(m0 + rrow) * KK;
    const int swR = (rrow >> 1) & 3;
    const uint32_t dstbase = (isA ? 0u : 2u * PL) + (uint32_t)rrow * ROWB;

    // precomputed ldsm offsets (stage-invariant)
    uint32_t offA[2][4], offB[2][2];
    {
        const int cbA = lane >> 4;
        #pragma unroll
        for (int mi = 0; mi < 4; mi++) {
            int r = mw * 64 + mi * 16 + (lane & 15);
            int sw = (r >> 1) & 3;
            #pragma unroll
            for (int kh = 0; kh < 2; kh++)
                offA[kh][mi] = (uint32_t)(r * ROWB + ((((kh * 2 + cbA) ^ sw) & 3) << 4));
        }
        const int cbB = (lane >> 3) & 1;
        const int gB  = (lane >> 4) & 1;
        #pragma unroll
        for (int q = 0; q < 2; q++) {
            int r = nw * 32 + (q * 2 + gB) * 8 + (lane & 7);
            int sw = (r >> 1) & 3;
            #pragma unroll
            for (int kh = 0; kh < 2; kh++)
                offB[kh][q] = (uint32_t)(r * ROWB + ((((kh * 2 + cbB) ^ sw) & 3) << 4));
        }
    }

    float acc[4][4][4];
    #pragma unroll
    for (int a = 0; a < 4; a++)
        #pragma unroll
        for (int b = 0; b < 4; b++)
            #pragma unroll
            for (int c = 0; c < 4; c++) acc[a][b][c] = 0.f;

    auto ISSUE = [&](int s) {
        const uint32_t stb = sbase + (uint32_t)(s % 3) * STG + dstbase;
        const int kt = s * 32;
        if (isA) {
            const __half* sh = wrh + kt;
            const __half* sl = wrl + kt;
            #pragma unroll
            for (int c = 0; c < 4; c++) {
                uint32_t d = stb + (uint32_t)(((c ^ swR) & 3) << 4);
                cpa16(d,      sh + c * 8, 16);
                cpa16(d + PL, sl + c * 8, 16);
            }
        } else {
            int kp  = kt / CIN;
            int ci0 = kt - kp * CIN;
            int tin = tB * STRIDE + kp - PAD;
            bool ok = cvB && tin >= 0 && tin < TIN;
            int tin_c = ok ? tin : 0;
            const __half* sh = xh + ((size_t)nbB * TIN + tin_c) * CIN + ci0;
            const __half* sl = xl + ((size_t)nbB * TIN + tin_c) * CIN + ci0;
            int sz = ok ? 16 : 0;
            #pragma unroll
            for (int c = 0; c < 4; c++) {
                uint32_t d = stb + (uint32_t)(((c ^ swR) & 3) << 4);
                cpa16(d,      sh + c * 8, sz);
                cpa16(d + PL, sl + c * 8, sz);
            }
        }
        cp_commit();
    };

    auto COMPUTE = [&](int st) {
        const uint32_t pA = sbase + (uint32_t)st * STG;
        const uint32_t pB = pA + 2u * PL;
        #pragma unroll
        for (int kh = 0; kh < 2; kh++) {
            uint32_t bH[4][2], bL[4][2];
            {
                uint32_t t[4];
                ldsm_x4(t, pB + offB[kh][0]);
                bH[0][0] = t[0]; bH[0][1] = t[1]; bH[1][0] = t[2]; bH[1][1] = t[3];
                ldsm_x4(t, pB + offB[kh][1]);
                bH[2][0] = t[0]; bH[2][1] = t[1]; bH[3][0] = t[2]; bH[3][1] = t[3];
                ldsm_x4(t, pB + PL + offB[kh][0]);
                bL[0][0] = t[0]; bL[0][1] = t[1]; bL[1][0] = t[2]; bL[1][1] = t[3];
                ldsm_x4(t, pB + PL + offB[kh][1]);
                bL[2][0] = t[0]; bL[2][1] = t[1]; bL[3][0] = t[2]; bL[3][1] = t[3];
            }
            #pragma unroll
            for (int mi = 0; mi < 4; mi++) {
                uint32_t aH[4], aL[4];
                ldsm_x4(aH, pA + offA[kh][mi]);
                ldsm_x4(aL, pA + PL + offA[kh][mi]);
                #pragma unroll
                for (int ni = 0; ni < 4; ni++) {
                    mma16816(acc[mi][ni], aH, bH[ni]);
                    mma16816(acc[mi][ni], aH, bL[ni]);
                    mma16816(acc[mi][ni], aL, bH[ni]);
                }
            }
        }
    };

    ISSUE(0);
    ISSUE(1);
    for (int s = 0; s < NS; s++) {
        if (s + 1 < NS) cp_wait1(); else cp_wait0();
        __syncthreads();
        if (s + 2 < NS) ISSUE(s + 2);
        COMPUTE(s % 3);
    }

    // epilogue: BN+ReLU -> channel-last hi/lo planes
    #pragma unroll
    for (int mi = 0; mi < 4; mi++) {
        int r1 = m0 + mw * 64 + mi * 16 + gid;
        int r2 = r1 + 8;
        float iv1 = inv[r1], bb1 = bet[r1];
        float iv2 = inv[r2], bb2 = bet[r2];
        #pragma unroll
        for (int ni = 0; ni < 4; ni++) {
            int nc = n0 + nw * 32 + ni * 8 + 2 * tig;
            #pragma unroll
            for (int q = 0; q < 2; q++) {
                int ncol = nc + q;
                if (ncol < NCOLS) {
                    float v1 = acc[mi][ni][q]     * iv1 + bb1;
                    float v2 = acc[mi][ni][2 + q] * iv2 + bb2;
                    v1 = v1 > 0.f ? v1 : 0.f;
                    v2 = v2 > 0.f ? v2 : 0.f;
                    size_t base = (size_t)ncol * NC;
                    splitstore(v1, &oh[base + r1], &ol[base + r1]);
                    splitstore(v2, &oh[base + r2], &ol[base + r2]);
                }
            }
        }
    }
}

__global__ __launch_bounds__(256, 2)
void conv1_k(const __half* xh, const __half* xl, const __half* wh, const __half* wl,
             const float* inv, const float* bet, __half* oh, __half* ol) {
    conv_cl_body<CIN1P, 3, 1, 0, T0, T1>(xh, xl, wh, wl, inv, bet, oh, ol);
}
__global__ __launch_bounds__(256, 2)
void conv2_k(const __half* xh, const __half* xl, const __half* wh, const __half* wl,
             const float* inv, const float* bet, __half* oh, __half* ol) {
    conv_cl_body<NC, 3, 1, 1, T1, T1>(xh, xl, wh, wl, inv, bet, oh, ol);
}
__global__ __launch_bounds__(256, 2)
void conv3_k(const __half* xh, const __half* xl, const __half* wh, const __half* wl,
             const float* inv, const float* bet, __half* oh, __half* ol) {
    conv_cl_body<NC, 4, 2, 1, T1, T2>(xh, xl, wh, wl, inv, bet, oh, ol);
}
__global__ __launch_bounds__(256, 2)
void conv45_k(const __half* xh, const __half* xl, const __half* wh, const __half* wl,
              const float* inv, const float* bet, __half* oh, __half* ol) {
    conv_cl_body<NC, 3, 1, 1, T2, T2>(xh, xl, wh, wl, inv, bet, oh, ol);
}

// ---------------- 1x1 projection + bias -> z [B, T', D] (channel-last input) ----------
__global__ __launch_bounds__(256)
void conv6_k(const __half* __restrict__ xh, const __half* __restrict__ xl,
             const float* __restrict__ w6, const float* __restrict__ b6,
             float* __restrict__ z)
{
    __shared__ float Xs[16][65];
    __shared__ float Ws[16][65];
    const int tx = threadIdx.x, ty = threadIdx.y;
    const int tid = ty * 16 + tx;
    const int t0 = blockIdx.x * 64;
    const int b  = blockIdx.y;

    float acc[4][4] = {};
    for (int c0 = 0; c0 < NC; c0 += 16) {
        #pragma unroll
        for (int j = 0; j < 4; j++) {
            int idx = tid + j * 256;
            int tl = idx >> 4, kk = idx & 15;
            int t = t0 + tl;
            float val = 0.f;
            if (t < T2) {
                size_t gi = ((size_t)b * T2 + t) * NC + c0 + kk;
                val = __half2float(xh[gi]) + __half2float(xl[gi]);
            }
            Xs[kk][tl] = val;
        }
        #pragma unroll
        for (int j = 0; j < 4; j++) {
            int idx = tid + j * 256;
            int dl = idx & 63, kk = idx >> 6;
            Ws[kk][dl] = w6[dl * NC + c0 + kk];
        }
        __syncthreads();
        #pragma unroll
        for (int k = 0; k < 16; k++) {
            float a[4], wv[4];
            #pragma unroll
            for (int i = 0; i < 4; i++) a[i] = Xs[k][ty * 4 + i];
            #pragma unroll
            for (int j = 0; j < 4; j++) wv[j] = Ws[k][tx * 4 + j];
            #pragma unroll
            for (int i = 0; i < 4; i++)
                #pragma unroll
                for (int j = 0; j < 4; j++)
                    acc[i][j] = fmaf(a[i], wv[j], acc[i][j]);
        }
        __syncthreads();
    }
    #pragma unroll
    for (int i = 0; i < 4; i++) {
        int t = t0 + ty * 4 + i;
        if (t < T2) {
            #pragma unroll
            for (int j = 0; j < 4; j++) {
                int d = tx * 4 + j;
                z[((size_t)b * T2 + t) * ND + d] = acc[i][j] + b6[d];
            }
        }
    }
}

// ---------------- VQ distance GEMM (fp32) ----------------
__global__ __launch_bounds__(256)
void dist_k(const float* __restrict__ emb)
{
    __shared__ float zs[64][65];
    __shared__ float es[64][65];
    const int tx = threadIdx.x, ty = threadIdx.y;
    const int tid = ty * 16 + tx;
    const int row0 = blockIdx.x * 64;
    const int e0   = blockIdx.y * 64;

    #pragma unroll
    for (int j = 0; j < 16; j++) {
        int idx = tid + j * 256;
        int k = idx & 63, r = idx >> 6;
        zs[r][k] = (row0 + r < NQ) ? g_z[(size_t)(row0 + r) * ND + k] : 0.f;
    }
    #pragma unroll
    for (int j = 0; j < 16; j++) {
        int idx = tid + j * 256;
        int k = idx & 63, e = idx >> 6;
        es[e][k] = emb[(size_t)(e0 + e) * ND + k];
    }
    __syncthreads();

    float acc[4][4] = {};
    #pragma unroll
    for (int k = 0; k < 64; k++) {
        float a[4], b[4];
        #pragma unroll
        for (int i = 0; i < 4; i++) a[i] = zs[ty * 4 + i][k];
        #pragma unroll
        for (int j = 0; j < 4; j++) b[j] = es[tx * 4 + j][k];
        #pragma unroll
        for (int i = 0; i < 4; i++)
            #pragma unroll
            for (int j = 0; j < 4; j++)
                acc[i][j] = fmaf(a[i], b[j], acc[i][j]);
    }

    #pragma unroll
    for (int i = 0; i < 4; i++) {
        int row = row0 + ty * 4 + i;
        if (row < NQ) {
            #pragma unroll
            for (int j = 0; j < 4; j++) {
                int e = e0 + tx * 4 + j;
                g_dist[(size_t)row * NM + e] = g_e2[e] - 2.f * acc[i][j];
            }
        }
    }
}

// ---------------- argmin + quantize + loss + counts ----------------
__global__ __launch_bounds__(256)
void vq_k(const float* __restrict__ emb, float* __restrict__ out_q)
{
    const int warp = threadIdx.x >> 5;
    const int lane = threadIdx.x & 31;
    const int row = blockIdx.x * 8 + warp;
    const float* dr = g_dist + (size_t)row * NM;

    float best = 3.4e38f; int bi = NM;
    #pragma unroll
    for (int i = 0; i < 16; i++) {
        int e = i * 32 + lane;
        float v = dr[e];
        if (v < best) { best = v; bi = e; }
    }
    #pragma unroll
    for (int off = 16; off > 0; off >>= 1) {
        float ob = __shfl_down_sync(0xffffffffu, best, off);
        int   oi = __shfl_down_sync(0xffffffffu, bi,   off);
        if (ob < best || (ob == best && oi < bi)) { best = ob; bi = oi; }
    }
    bi = __shfl_sync(0xffffffffu, bi, 0);

    const float* zr = g_z + (size_t)row * ND;
    const float* er = emb + (size_t)bi * ND;
    float lsum = 0.f;
    #pragma unroll
    for (int d0 = 0; d0 < ND; d0 += 32) {
        int d = d0 + lane;
        float zv = zr[d], qv = er[d];
        out_q[(size_t)row * ND + d] = zv + (qv - zv);
        float df = zv - qv;
        lsum += df * df;
    }
    #pragma unroll
    for (int off = 16; off > 0; off >>= 1)
        lsum += __shfl_down_sync(0xffffffffu, lsum, off);
    if (lane == 0) {
        atomicAdd(&g_loss[0], lsum);
        atomicAdd(&g_counts[bi], 1);
    }
}

__global__ void finalize_k(float* __restrict__ out)
{
    __shared__ float sh[NM];
    int tid = threadIdx.x;
    float p = (float)g_counts[tid] / (float)NQ;
    sh[tid] = -p * logf(p + 1e-10f);
    __syncthreads();
    for (int s = NM / 2; s > 0; s >>= 1) {
        if (tid < s) sh[tid] += sh[tid + s];
        __syncthreads();
    }
    if (tid == 0) {
        out[NQE]     = 0.25f * g_loss[0] / (float)NQE;
        out[NQE + 1] = expf(sh[0]);
    }
}

// ---------------- host-side driver ----------------
static void encoder_run(const float* mels, const float* w1, const float* w2,
                        const float* w3, const float* w4, const float* w5,
                        const float* w6, const float* b6,
                        const float* bng, const float* bnb,
                        const float* bnm, const float* bnv,
                        const float* emb, float* out)
{
    __half *mh, *ml, *pAh, *pAl, *pBh, *pBl;
    __half *w1h, *w1l, *w2h, *w2l, *w3h, *w3l, *w4h, *w4l, *w5h, *w5l;
    float *zbuf, *bnInv, *bnBeta;
    cudaGetSymbolAddress((void**)&mh, g_m_h);   cudaGetSymbolAddress((void**)&ml, g_m_l);
    cudaGetSymbolAddress((void**)&pAh, g_pA_h); cudaGetSymbolAddress((void**)&pAl, g_pA_l);
    cudaGetSymbolAddress((void**)&pBh, g_pB_h); cudaGetSymbolAddress((void**)&pBl, g_pB_l);
    cudaGetSymbolAddress((void**)&w1h, g_w1h);  cudaGetSymbolAddress((void**)&w1l, g_w1l);
    cudaGetSymbolAddress((void**)&w2h, g_w2h);  cudaGetSymbolAddress((void**)&w2l, g_w2l);
    cudaGetSymbolAddress((void**)&w3h, g_w3h);  cudaGetSymbolAddress((void**)&w3l, g_w3l);
    cudaGetSymbolAddress((void**)&w4h, g_w4h);  cudaGetSymbolAddress((void**)&w4l, g_w4l);
    cudaGetSymbolAddress((void**)&w5h, g_w5h);  cudaGetSymbolAddress((void**)&w5l, g_w5l);
    cudaGetSymbolAddress((void**)&zbuf, g_z);
    cudaGetSymbolAddress((void**)&bnInv,  g_bnInv);
    cudaGetSymbolAddress((void**)&bnBeta, g_bnBeta);

    cudaFuncSetAttribute(conv1_k,  cudaFuncAttributeMaxDynamicSharedMemorySize, SMEM2);
    cudaFuncSetAttribute(conv2_k,  cudaFuncAttributeMaxDynamicSharedMemorySize, SMEM2);
    cudaFuncSetAttribute(conv3_k,  cudaFuncAttributeMaxDynamicSharedMemorySize, SMEM2);
    cudaFuncSetAttribute(conv45_k, cudaFuncAttributeMaxDynamicSharedMemorySize, SMEM2);

    // launch 0: prep;  launch 1: pack;  launch 2: conv1;  launch 3: conv2 (ncu target)
    prep_k<<<(5 * NC + 255) / 256, 256>>>(bng, bnb, bnm, bnv, emb);
    packall_k<<<(PACKALL_N + 255) / 256, 256>>>(w1, w2, w3, w4, w5, mels);

    conv1_k<<<dim3((NB * T1 + 127) / 128, NC / 128), 256, SMEM2>>>(
        mh, ml, w1h, w1l, bnInv + 0 * NC, bnBeta + 0 * NC, pAh, pAl);
    conv2_k<<<dim3((NB * T1 + 127) / 128, NC / 128), 256, SMEM2>>>(
        pAh, pAl, w2h, w2l, bnInv + 1 * NC, bnBeta + 1 * NC, pBh, pBl);
    conv3_k<<<dim3((NB * T2 + 127) / 128, NC / 128), 256, SMEM2>>>(
        pBh, pBl, w3h, w3l, bnInv + 2 * NC, bnBeta + 2 * NC, pAh, pAl);
    conv45_k<<<dim3((NB * T2 + 127) / 128, NC / 128), 256, SMEM2>>>(
        pAh, pAl, w4h, w4l, bnInv + 3 * NC, bnBeta + 3 * NC, pBh, pBl);
    conv45_k<<<dim3((NB * T2 + 127) / 128, NC / 128), 256, SMEM2>>>(
        pBh, pBl, w5h, w5l, bnInv + 4 * NC, bnBeta + 4 * NC, pAh, pAl);
    conv6_k<<<dim3((T2 + 63) / 64, NB), dim3(16, 16)>>>(pAh, pAl, w6, b6, zbuf);
    dist_k<<<dim3((NQ + 63) / 64, NM / 64), dim3(16, 16)>>>(emb);
    vq_k<<<NQ / 8, 256>>>(emb, out);
    finalize_k<<<1, NM>>>(out);
}

extern "C" void kernel_launch(void* const* d_in, const int* in_sizes, int n_in,
                              void* d_out, int out_size)
{
    encoder_run((const float*)d_in[0], (const float*)d_in[1], (const float*)d_in[2],
                (const float*)d_in[3], (const float*)d_in[4], (const float*)d_in[5],
                (const float*)d_in[6], (const float*)d_in[7], (const float*)d_in[8],
                (const float*)d_in[9], (const float*)d_in[10], (const float*)d_in[11],
                (const float*)d_in[12], (float*)d_out);
}